// round 10
// baseline (speedup 1.0000x reference)
#include <cuda_runtime.h>
#include <math.h>

// ---------------- scratch (device globals; no allocation allowed) ----------------
__device__ __align__(16) float g_q[2 * 12 * 8192 * 64];
__device__ __align__(16) float g_k[2 * 12 * 8192 * 64];
__device__ __align__(16) float g_v[2 * 12 * 8192 * 64];
__device__ __align__(16) float g_attn[16384 * 768];
__device__ __align__(16) float g_P[511 * 768];
__device__ __align__(16) float g_RK[511 * 768];

// ---------------- positional embedding (511 x 768) ----------------
__global__ void pos_kernel(float* __restrict__ P) {
    int row = blockIdx.x;        // 0..510  (distance = row - 255)
    int f = threadIdx.x;         // 0..127  (nb = 128)
    float dist = (float)(row - 255);
    float absd = fabsf(dist);

    // exponential basis
    float hl = exp2f(3.0f + (float)f * (5.0f / 127.0f));
    float fe = expf(-(0.6931471805599453f / hl) * absd);
    // central mask basis
    float cw = exp2f((float)(f + 1)) - 1.0f;
    float fc = (cw > absd) ? 1.0f : 0.0f;
    // gamma pdf basis (double: huge exponent cancellation)
    double mean = 2.0 + 2.0 * (double)f;      // linspace(2,256,128)
    double conc = mean * mean;                // stddev = 1
    double lu;
    if (absd > 0.0f) lu = (conc - 1.0) * log((double)absd) - mean * (double)absd;
    else             lu = -INFINITY;          // xlogy with nonzero x, y=0
    double lnorm = lgamma(conc) - conc * log(mean);
    double prob = exp(lu - lnorm) + 1e-8;

    __shared__ double red[128];
    red[f] = prob;
    __syncthreads();
    for (int s = 64; s > 0; s >>= 1) {
        if (f < s) red[f] = fmax(red[f], red[f + s]);
        __syncthreads();
    }
    double mp = red[0];
    float fg = (float)(prob / mp);

    float sgn = (dist > 0.f) ? 1.f : ((dist < 0.f) ? -1.f : 0.f);
    float* Pr = P + (size_t)row * 768;
    Pr[f]       = fe;  Pr[128 + f] = fc;        Pr[256 + f] = fg;
    Pr[384 + f] = sgn * fe; Pr[512 + f] = sgn * fc; Pr[640 + f] = sgn * fg;
}

// ---------------- generic fp32 GEMM: C = A(MxK) * B(KxN) (+bias), 128x128x16 tiles ----------------
__global__ __launch_bounds__(256, 2) void gemm_bias_kernel(
    const float* __restrict__ A, const float* __restrict__ B,
    float* __restrict__ C, const float* __restrict__ bias,
    int M, int N, int K)
{
    __shared__ float As[16 * 132];   // transposed [k][m], stride 132
    __shared__ float Bs[16 * 128];   // [k][n]
    int tid = threadIdx.x;
    int ty = tid >> 4, tx = tid & 15;
    int row0 = blockIdx.y * 128;
    int col0 = blockIdx.x * 128;
    float acc[8][8] = {};

    for (int kt = 0; kt < K; kt += 16) {
#pragma unroll
        for (int i = 0; i < 2; ++i) {
            int lin = tid + i * 256;
            int m = lin >> 2, kq = (lin & 3) * 4;
            float4 v = make_float4(0.f, 0.f, 0.f, 0.f);
            if (row0 + m < M)
                v = *(const float4*)(A + (size_t)(row0 + m) * K + kt + kq);
            As[(kq + 0) * 132 + m] = v.x;
            As[(kq + 1) * 132 + m] = v.y;
            As[(kq + 2) * 132 + m] = v.z;
            As[(kq + 3) * 132 + m] = v.w;
        }
#pragma unroll
        for (int i = 0; i < 2; ++i) {
            int lin = tid + i * 256;
            int kk = lin >> 5, nq = (lin & 31) * 4;
            *(float4*)(Bs + kk * 128 + nq) =
                *(const float4*)(B + (size_t)(kt + kk) * N + col0 + nq);
        }
        __syncthreads();
#pragma unroll
        for (int kk = 0; kk < 16; ++kk) {
            float a[8], b[8];
            *(float4*)(a)     = *(float4*)(As + kk * 132 + ty * 8);
            *(float4*)(a + 4) = *(float4*)(As + kk * 132 + ty * 8 + 4);
            *(float4*)(b)     = *(float4*)(Bs + kk * 128 + tx * 8);
            *(float4*)(b + 4) = *(float4*)(Bs + kk * 128 + tx * 8 + 4);
#pragma unroll
            for (int r = 0; r < 8; ++r)
#pragma unroll
                for (int c = 0; c < 8; ++c)
                    acc[r][c] = fmaf(a[r], b[c], acc[r][c]);
        }
        __syncthreads();
    }

    float bb[8] = {};
    if (bias) {
#pragma unroll
        for (int c = 0; c < 8; ++c) bb[c] = bias[col0 + tx * 8 + c];
    }
#pragma unroll
    for (int r = 0; r < 8; ++r) {
        int row = row0 + ty * 8 + r;
        if (row < M) {
#pragma unroll
            for (int c = 0; c < 8; ++c)
                C[(size_t)row * N + col0 + tx * 8 + c] = acc[r][c] + bb[c];
        }
    }
}

// ---------------- QKV GEMM with (h,d,sel) scatter into (B,H,N,D) layout ----------------
__global__ __launch_bounds__(256, 2) void gemm_qkv_kernel(
    const float* __restrict__ A, const float* __restrict__ B)
{
    // M=16384, N=2304, K=768 (exact multiples; no guards)
    __shared__ float As[16 * 132];
    __shared__ float Bs[16 * 128];
    int tid = threadIdx.x;
    int ty = tid >> 4, tx = tid & 15;
    int row0 = blockIdx.y * 128;
    int col0 = blockIdx.x * 128;
    float acc[8][8] = {};

    for (int kt = 0; kt < 768; kt += 16) {
#pragma unroll
        for (int i = 0; i < 2; ++i) {
            int lin = tid + i * 256;
            int m = lin >> 2, kq = (lin & 3) * 4;
            float4 v = *(const float4*)(A + (size_t)(row0 + m) * 768 + kt + kq);
            As[(kq + 0) * 132 + m] = v.x;
            As[(kq + 1) * 132 + m] = v.y;
            As[(kq + 2) * 132 + m] = v.z;
            As[(kq + 3) * 132 + m] = v.w;
        }
#pragma unroll
        for (int i = 0; i < 2; ++i) {
            int lin = tid + i * 256;
            int kk = lin >> 5, nq = (lin & 31) * 4;
            *(float4*)(Bs + kk * 128 + nq) =
                *(const float4*)(B + (size_t)(kt + kk) * 2304 + col0 + nq);
        }
        __syncthreads();
#pragma unroll
        for (int kk = 0; kk < 16; ++kk) {
            float a[8], b[8];
            *(float4*)(a)     = *(float4*)(As + kk * 132 + ty * 8);
            *(float4*)(a + 4) = *(float4*)(As + kk * 132 + ty * 8 + 4);
            *(float4*)(b)     = *(float4*)(Bs + kk * 128 + tx * 8);
            *(float4*)(b + 4) = *(float4*)(Bs + kk * 128 + tx * 8 + 4);
#pragma unroll
            for (int r = 0; r < 8; ++r)
#pragma unroll
                for (int c = 0; c < 8; ++c)
                    acc[r][c] = fmaf(a[r], b[c], acc[r][c]);
        }
        __syncthreads();
    }

#pragma unroll
    for (int c = 0; c < 8; ++c) {
        int col = col0 + tx * 8 + c;          // col = h*192 + d*3 + sel
        int h = col / 192;
        int rem = col - h * 192;
        int d = rem / 3;
        int sel = rem - d * 3;
        float* dst = (sel == 0) ? g_q : (sel == 1) ? g_k : g_v;
#pragma unroll
        for (int r = 0; r < 8; ++r) {
            int row = row0 + ty * 8 + r;      // row = batch*8192 + n
            int bidx = row >> 13, n = row & 8191;
            dst[((size_t)(bidx * 12 + h) * 8192 + n) * 64 + d] = acc[r][c];
        }
    }
}

// ---------------- fused windowed attention ----------------
// grid: (qt=4, w=32, bh=24); block 256
// smem: sG 20544f (relK slab [d][u]/G [ii][u] str321 -> Pt [j][ii] str66)
//       sK 17408f (K [d][j] str260 -> V [j][d] str68)
//       sQc 4352f, sQp 4352f ([d][ii] str68). total 46656 floats = 186624 B
#define ATTN_SMEM_FLOATS 46656
__global__ __launch_bounds__(256, 1) void attn_kernel(
    const float* __restrict__ RK,
    const float* __restrict__ rcb,
    const float* __restrict__ rpb)
{
    extern __shared__ float sm[];
    float* sG  = sm;
    float* sK  = sm + 20544;
    float* sQc = sm + 20544 + 17408;
    float* sQp = sQc + 4352;

    int qt = blockIdx.x, w = blockIdx.y, bh = blockIdx.z;
    int bb = bh / 12;
    int h = bh - bb * 12;
    int tid = threadIdx.x;

    const float* qbase = g_q + ((size_t)bh * 8192 + w * 256 + qt * 64) * 64;
    const float* kbase = g_k + ((size_t)bh * 8192 + w * 256) * 64;
    const float* vbase = g_v + ((size_t)bh * 8192 + w * 256) * 64;

    // ---- phase 0: stage Qc/Qp, K, relK slab ----
#pragma unroll
    for (int it = 0; it < 4; ++it) {
        int e = (it * 256 + tid) * 4;
        int ii = e >> 6, d = e & 63;
        float4 qv = *(const float4*)(qbase + ii * 64 + d);
        float4 cb = *(const float4*)(rcb + h * 64 + d);
        float4 pb = *(const float4*)(rpb + h * 64 + d);
        sQc[(d + 0) * 68 + ii] = (qv.x + cb.x) * 0.125f;
        sQc[(d + 1) * 68 + ii] = (qv.y + cb.y) * 0.125f;
        sQc[(d + 2) * 68 + ii] = (qv.z + cb.z) * 0.125f;
        sQc[(d + 3) * 68 + ii] = (qv.w + cb.w) * 0.125f;
        sQp[(d + 0) * 68 + ii] = qv.x + pb.x;
        sQp[(d + 1) * 68 + ii] = qv.y + pb.y;
        sQp[(d + 2) * 68 + ii] = qv.z + pb.z;
        sQp[(d + 3) * 68 + ii] = qv.w + pb.w;
    }
#pragma unroll
    for (int it = 0; it < 16; ++it) {
        int e = (it * 256 + tid) * 4;
        int j = e >> 6, d = e & 63;
        float4 kv = *(const float4*)(kbase + j * 64 + d);
        sK[(d + 0) * 260 + j] = kv.x;
        sK[(d + 1) * 260 + j] = kv.y;
        sK[(d + 2) * 260 + j] = kv.z;
        sK[(d + 3) * 260 + j] = kv.w;
    }
    int base_rel = 192 - qt * 64;
    const float* RKh = RK + h * 64;
#pragma unroll
    for (int it = 0; it < 20; ++it) {
        int e = (it * 256 + tid) * 4;
        int u = e >> 6, d = e & 63;
        int idx = base_rel + u;
        float4 rv = make_float4(0.f, 0.f, 0.f, 0.f);
        if (idx < 511) rv = *(const float4*)(RKh + (size_t)idx * 768 + d);
        sG[(d + 0) * 321 + u] = rv.x;
        sG[(d + 1) * 321 + u] = rv.y;
        sG[(d + 2) * 321 + u] = rv.z;
        sG[(d + 3) * 321 + u] = rv.w;
    }
    __syncthreads();

    // ---- phase G: G[ii][u] = Qp . relK_slab  (64 x 320 x 64) ----
    {
        int gy = tid >> 5, gx = tid & 31;
        float accG[8][10] = {};
        for (int d = 0; d < 64; ++d) {
            float a[8];
            *(float4*)(a)     = *(float4*)(sQp + d * 68 + gy * 8);
            *(float4*)(a + 4) = *(float4*)(sQp + d * 68 + gy * 8 + 4);
            float bv[10];
#pragma unroll
            for (int c = 0; c < 10; ++c) bv[c] = sG[d * 321 + gx * 10 + c];
#pragma unroll
            for (int r = 0; r < 8; ++r)
#pragma unroll
                for (int c = 0; c < 10; ++c)
                    accG[r][c] = fmaf(a[r], bv[c], accG[r][c]);
        }
        __syncthreads();   // everyone done reading relK slab
#pragma unroll
        for (int r = 0; r < 8; ++r)
#pragma unroll
            for (int c = 0; c < 10; ++c)
                sG[(gy * 8 + r) * 321 + gx * 10 + c] = accG[r][c];
    }
    __syncthreads();

    // ---- phase S: scores = Qc . K^T + gather(G), softmax (intra-warp) ----
    int ty = tid >> 5, tx = tid & 31;     // warp = 8 rows, lanes split 256 cols
    float acc[8][8] = {};
    for (int d = 0; d < 64; ++d) {
        float a[8], b[8];
        *(float4*)(a)     = *(float4*)(sQc + d * 68 + ty * 8);
        *(float4*)(a + 4) = *(float4*)(sQc + d * 68 + ty * 8 + 4);
        *(float4*)(b)     = *(float4*)(sK + d * 260 + tx * 8);
        *(float4*)(b + 4) = *(float4*)(sK + d * 260 + tx * 8 + 4);
#pragma unroll
        for (int r = 0; r < 8; ++r)
#pragma unroll
            for (int c = 0; c < 8; ++c)
                acc[r][c] = fmaf(a[r], b[c], acc[r][c]);
    }
#pragma unroll
    for (int r = 0; r < 8; ++r) {
        int ii = ty * 8 + r;
        const float* grow = sG + ii * 321 + (tx * 8 - ii + 63);  // u = j - ii + 63
#pragma unroll
        for (int c = 0; c < 8; ++c) acc[r][c] += grow[c];
    }
#pragma unroll
    for (int r = 0; r < 8; ++r) {
        float m = acc[r][0];
#pragma unroll
        for (int c = 1; c < 8; ++c) m = fmaxf(m, acc[r][c]);
#pragma unroll
        for (int off = 16; off > 0; off >>= 1)
            m = fmaxf(m, __shfl_xor_sync(0xffffffffu, m, off));
        float s = 0.f;
#pragma unroll
        for (int c = 0; c < 8; ++c) { acc[r][c] = expf(acc[r][c] - m); s += acc[r][c]; }
#pragma unroll
        for (int off = 16; off > 0; off >>= 1)
            s += __shfl_xor_sync(0xffffffffu, s, off);
        float inv = 1.0f / s;
#pragma unroll
        for (int c = 0; c < 8; ++c) acc[r][c] *= inv;
    }
    __syncthreads();  // all gather reads of G / K reads done

    // ---- phase AV: Pt into sG, V into sK, O = P . V ----
#pragma unroll
    for (int r = 0; r < 8; ++r)
#pragma unroll
        for (int c = 0; c < 8; ++c)
            sG[(tx * 8 + c) * 66 + ty * 8 + r] = acc[r][c];
#pragma unroll
    for (int it = 0; it < 16; ++it) {
        int e = (it * 256 + tid) * 4;
        int j = e >> 6, d = e & 63;
        *(float4*)(sK + j * 68 + d) = *(const float4*)(vbase + j * 64 + d);
    }
    __syncthreads();

    int oy = tid >> 4, ox = tid & 15;
    float o[4][4] = {};
    for (int j = 0; j < 256; ++j) {
        float p[4];
        *(float2*)(p)     = *(float2*)(sG + j * 66 + oy * 4);
        *(float2*)(p + 2) = *(float2*)(sG + j * 66 + oy * 4 + 2);
        float4 bv4 = *(float4*)(sK + j * 68 + ox * 4);
        o[0][0] = fmaf(p[0], bv4.x, o[0][0]); o[0][1] = fmaf(p[0], bv4.y, o[0][1]);
        o[0][2] = fmaf(p[0], bv4.z, o[0][2]); o[0][3] = fmaf(p[0], bv4.w, o[0][3]);
        o[1][0] = fmaf(p[1], bv4.x, o[1][0]); o[1][1] = fmaf(p[1], bv4.y, o[1][1]);
        o[1][2] = fmaf(p[1], bv4.z, o[1][2]); o[1][3] = fmaf(p[1], bv4.w, o[1][3]);
        o[2][0] = fmaf(p[2], bv4.x, o[2][0]); o[2][1] = fmaf(p[2], bv4.y, o[2][1]);
        o[2][2] = fmaf(p[2], bv4.z, o[2][2]); o[2][3] = fmaf(p[2], bv4.w, o[2][3]);
        o[3][0] = fmaf(p[3], bv4.x, o[3][0]); o[3][1] = fmaf(p[3], bv4.y, o[3][1]);
        o[3][2] = fmaf(p[3], bv4.z, o[3][2]); o[3][3] = fmaf(p[3], bv4.w, o[3][3]);
    }
    float* out0 = g_attn + ((size_t)bb * 8192 + w * 256 + qt * 64) * 768 + h * 64;
#pragma unroll
    for (int r = 0; r < 4; ++r) {
        float4 ov = make_float4(o[r][0], o[r][1], o[r][2], o[r][3]);
        *(float4*)(out0 + (size_t)(oy * 4 + r) * 768 + ox * 4) = ov;
    }
}

// ---------------- launch ----------------
extern "C" void kernel_launch(void* const* d_in, const int* in_sizes, int n_in,
                              void* d_out, int out_size)
{
    const float* x    = (const float*)d_in[0];
    const float* wqkv = (const float*)d_in[1];
    const float* wout = (const float*)d_in[2];
    const float* bout = (const float*)d_in[3];
    const float* wrel = (const float*)d_in[4];
    const float* rcb  = (const float*)d_in[5];
    const float* rpb  = (const float*)d_in[6];
    float* out = (float*)d_out;

    float *P, *RK, *attn;
    cudaGetSymbolAddress((void**)&P,    g_P);
    cudaGetSymbolAddress((void**)&RK,   g_RK);
    cudaGetSymbolAddress((void**)&attn, g_attn);

    const int SMEM_BYTES = ATTN_SMEM_FLOATS * 4;  // 186624
    cudaFuncSetAttribute(attn_kernel,
                         cudaFuncAttributeMaxDynamicSharedMemorySize, SMEM_BYTES);

    // 1) positional embedding
    pos_kernel<<<511, 128>>>(P);
    // 2) rel_k = P @ w_rel   (511 x 768 x 768)
    gemm_bias_kernel<<<dim3(6, 4), 256>>>(P, wrel, RK, nullptr, 511, 768, 768);
    // 3) qkv projection with scatter to (B,H,N,D)
    gemm_qkv_kernel<<<dim3(18, 128), 256>>>(x, wqkv);
    // 4) fused windowed attention
    attn_kernel<<<dim3(4, 32, 24), 256, SMEM_BYTES>>>(RK, rcb, rpb);
    // 5) output projection + bias
    gemm_bias_kernel<<<dim3(6, 128), 256>>>(attn, wout, out, bout, 16384, 768, 768);
}

// round 12
// speedup vs baseline: 1.0798x; 1.0798x over previous
#include <cuda_runtime.h>
#include <math.h>

// ---------------- scratch (device globals; no allocation allowed) ----------------
__device__ __align__(16) float g_q[2 * 12 * 8192 * 64];
__device__ __align__(16) float g_k[2 * 12 * 8192 * 64];
__device__ __align__(16) float g_v[2 * 12 * 8192 * 64];
__device__ __align__(16) float g_attn[16384 * 768];
__device__ __align__(16) float g_P[511 * 768];
__device__ __align__(16) float g_RK[511 * 768];

// ---------------- positional embedding (511 x 768) ----------------
__global__ void pos_kernel(float* __restrict__ P) {
    int row = blockIdx.x;        // 0..510  (distance = row - 255)
    int f = threadIdx.x;         // 0..127  (nb = 128)
    float dist = (float)(row - 255);
    float absd = fabsf(dist);

    float hl = exp2f(3.0f + (float)f * (5.0f / 127.0f));
    float fe = expf(-(0.6931471805599453f / hl) * absd);
    float cw = exp2f((float)(f + 1)) - 1.0f;
    float fc = (cw > absd) ? 1.0f : 0.0f;
    double mean = 2.0 + 2.0 * (double)f;
    double conc = mean * mean;
    double lu;
    if (absd > 0.0f) lu = (conc - 1.0) * log((double)absd) - mean * (double)absd;
    else             lu = -INFINITY;
    double lnorm = lgamma(conc) - conc * log(mean);
    double prob = exp(lu - lnorm) + 1e-8;

    __shared__ double red[128];
    red[f] = prob;
    __syncthreads();
    for (int s = 64; s > 0; s >>= 1) {
        if (f < s) red[f] = fmax(red[f], red[f + s]);
        __syncthreads();
    }
    double mp = red[0];
    float fg = (float)(prob / mp);

    float sgn = (dist > 0.f) ? 1.f : ((dist < 0.f) ? -1.f : 0.f);
    float* Pr = P + (size_t)row * 768;
    Pr[f]       = fe;  Pr[128 + f] = fc;        Pr[256 + f] = fg;
    Pr[384 + f] = sgn * fe; Pr[512 + f] = sgn * fc; Pr[640 + f] = sgn * fg;
}

// ---------------- generic fp32 GEMM, double-buffered 128x128x16 ----------------
__global__ __launch_bounds__(256, 2) void gemm_bias_kernel(
    const float* __restrict__ A, const float* __restrict__ B,
    float* __restrict__ C, const float* __restrict__ bias,
    int M, int N, int K)
{
    __shared__ float As[2][16 * 132];   // transposed [k][m]
    __shared__ float Bs[2][16 * 128];   // [k][n]
    int tid = threadIdx.x;
    int ty = tid >> 4, tx = tid & 15;
    int row0 = blockIdx.y * 128, col0 = blockIdx.x * 128;
    float acc[8][8] = {};

    int mA = tid >> 2, kA = (tid & 3) * 4;     // chunk0 rows 0..63, chunk1 +64
    int kB = tid >> 5, nB = (tid & 31) * 4;    // chunk0 k 0..7,  chunk1 +8

    const float* Ap0 = A + (size_t)(row0 + mA) * K + kA;
    const float* Ap1 = Ap0 + (size_t)64 * K;
    const float* Bp0 = B + (size_t)kB * N + col0 + nB;
    const float* Bp1 = Bp0 + (size_t)8 * N;
    bool ga0 = (row0 + mA) < M;
    bool ga1 = (row0 + mA + 64) < M;
    const float4 z4 = make_float4(0.f, 0.f, 0.f, 0.f);

    float4 ra0 = ga0 ? *(const float4*)(Ap0) : z4;
    float4 ra1 = ga1 ? *(const float4*)(Ap1) : z4;
    float4 rb0 = *(const float4*)(Bp0);
    float4 rb1 = *(const float4*)(Bp1);
    int p = 0;
    {
        float* as = As[0]; float* bs = Bs[0];
        as[(kA + 0) * 132 + mA] = ra0.x; as[(kA + 1) * 132 + mA] = ra0.y;
        as[(kA + 2) * 132 + mA] = ra0.z; as[(kA + 3) * 132 + mA] = ra0.w;
        as[(kA + 0) * 132 + mA + 64] = ra1.x; as[(kA + 1) * 132 + mA + 64] = ra1.y;
        as[(kA + 2) * 132 + mA + 64] = ra1.z; as[(kA + 3) * 132 + mA + 64] = ra1.w;
        *(float4*)(bs + kB * 128 + nB) = rb0;
        *(float4*)(bs + (kB + 8) * 128 + nB) = rb1;
    }
    __syncthreads();

    for (int kt = 16; kt < K; kt += 16) {
        ra0 = ga0 ? *(const float4*)(Ap0 + kt) : z4;
        ra1 = ga1 ? *(const float4*)(Ap1 + kt) : z4;
        rb0 = *(const float4*)(Bp0 + (size_t)kt * N);
        rb1 = *(const float4*)(Bp1 + (size_t)kt * N);
        {
            const float* as = As[p]; const float* bs = Bs[p];
#pragma unroll
            for (int kk = 0; kk < 16; ++kk) {
                float a[8], b[8];
                *(float4*)(a)     = *(const float4*)(as + kk * 132 + ty * 8);
                *(float4*)(a + 4) = *(const float4*)(as + kk * 132 + ty * 8 + 4);
                *(float4*)(b)     = *(const float4*)(bs + kk * 128 + tx * 8);
                *(float4*)(b + 4) = *(const float4*)(bs + kk * 128 + tx * 8 + 4);
#pragma unroll
                for (int r = 0; r < 8; ++r)
#pragma unroll
                    for (int c = 0; c < 8; ++c)
                        acc[r][c] = fmaf(a[r], b[c], acc[r][c]);
            }
        }
        {
            float* as = As[p ^ 1]; float* bs = Bs[p ^ 1];
            as[(kA + 0) * 132 + mA] = ra0.x; as[(kA + 1) * 132 + mA] = ra0.y;
            as[(kA + 2) * 132 + mA] = ra0.z; as[(kA + 3) * 132 + mA] = ra0.w;
            as[(kA + 0) * 132 + mA + 64] = ra1.x; as[(kA + 1) * 132 + mA + 64] = ra1.y;
            as[(kA + 2) * 132 + mA + 64] = ra1.z; as[(kA + 3) * 132 + mA + 64] = ra1.w;
            *(float4*)(bs + kB * 128 + nB) = rb0;
            *(float4*)(bs + (kB + 8) * 128 + nB) = rb1;
        }
        __syncthreads();
        p ^= 1;
    }
    {
        const float* as = As[p]; const float* bs = Bs[p];
#pragma unroll
        for (int kk = 0; kk < 16; ++kk) {
            float a[8], b[8];
            *(float4*)(a)     = *(const float4*)(as + kk * 132 + ty * 8);
            *(float4*)(a + 4) = *(const float4*)(as + kk * 132 + ty * 8 + 4);
            *(float4*)(b)     = *(const float4*)(bs + kk * 128 + tx * 8);
            *(float4*)(b + 4) = *(const float4*)(bs + kk * 128 + tx * 8 + 4);
#pragma unroll
            for (int r = 0; r < 8; ++r)
#pragma unroll
                for (int c = 0; c < 8; ++c)
                    acc[r][c] = fmaf(a[r], b[c], acc[r][c]);
        }
    }

    float bb[8] = {};
    if (bias) {
#pragma unroll
        for (int c = 0; c < 8; ++c) bb[c] = bias[col0 + tx * 8 + c];
    }
#pragma unroll
    for (int r = 0; r < 8; ++r) {
        int row = row0 + ty * 8 + r;
        if (row < M) {
#pragma unroll
            for (int c = 0; c < 8; ++c)
                C[(size_t)row * N + col0 + tx * 8 + c] = acc[r][c] + bb[c];
        }
    }
}

// ---------------- QKV GEMM (16384x2304x768), double-buffered, scatter epilogue ----------------
__global__ __launch_bounds__(256, 2) void gemm_qkv_kernel(
    const float* __restrict__ A, const float* __restrict__ B)
{
    __shared__ float As[2][16 * 132];
    __shared__ float Bs[2][16 * 128];
    int tid = threadIdx.x;
    int ty = tid >> 4, tx = tid & 15;
    int row0 = blockIdx.y * 128, col0 = blockIdx.x * 128;
    float acc[8][8] = {};

    int mA = tid >> 2, kA = (tid & 3) * 4;
    int kB = tid >> 5, nB = (tid & 31) * 4;
    const float* Ap0 = A + (size_t)(row0 + mA) * 768 + kA;
    const float* Ap1 = Ap0 + (size_t)64 * 768;
    const float* Bp0 = B + (size_t)kB * 2304 + col0 + nB;
    const float* Bp1 = Bp0 + (size_t)8 * 2304;

    float4 ra0 = *(const float4*)(Ap0);
    float4 ra1 = *(const float4*)(Ap1);
    float4 rb0 = *(const float4*)(Bp0);
    float4 rb1 = *(const float4*)(Bp1);
    int p = 0;
    {
        float* as = As[0]; float* bs = Bs[0];
        as[(kA + 0) * 132 + mA] = ra0.x; as[(kA + 1) * 132 + mA] = ra0.y;
        as[(kA + 2) * 132 + mA] = ra0.z; as[(kA + 3) * 132 + mA] = ra0.w;
        as[(kA + 0) * 132 + mA + 64] = ra1.x; as[(kA + 1) * 132 + mA + 64] = ra1.y;
        as[(kA + 2) * 132 + mA + 64] = ra1.z; as[(kA + 3) * 132 + mA + 64] = ra1.w;
        *(float4*)(bs + kB * 128 + nB) = rb0;
        *(float4*)(bs + (kB + 8) * 128 + nB) = rb1;
    }
    __syncthreads();

    for (int kt = 16; kt < 768; kt += 16) {
        ra0 = *(const float4*)(Ap0 + kt);
        ra1 = *(const float4*)(Ap1 + kt);
        rb0 = *(const float4*)(Bp0 + (size_t)kt * 2304);
        rb1 = *(const float4*)(Bp1 + (size_t)kt * 2304);
        {
            const float* as = As[p]; const float* bs = Bs[p];
#pragma unroll
            for (int kk = 0; kk < 16; ++kk) {
                float a[8], b[8];
                *(float4*)(a)     = *(const float4*)(as + kk * 132 + ty * 8);
                *(float4*)(a + 4) = *(const float4*)(as + kk * 132 + ty * 8 + 4);
                *(float4*)(b)     = *(const float4*)(bs + kk * 128 + tx * 8);
                *(float4*)(b + 4) = *(const float4*)(bs + kk * 128 + tx * 8 + 4);
#pragma unroll
                for (int r = 0; r < 8; ++r)
#pragma unroll
                    for (int c = 0; c < 8; ++c)
                        acc[r][c] = fmaf(a[r], b[c], acc[r][c]);
            }
        }
        {
            float* as = As[p ^ 1]; float* bs = Bs[p ^ 1];
            as[(kA + 0) * 132 + mA] = ra0.x; as[(kA + 1) * 132 + mA] = ra0.y;
            as[(kA + 2) * 132 + mA] = ra0.z; as[(kA + 3) * 132 + mA] = ra0.w;
            as[(kA + 0) * 132 + mA + 64] = ra1.x; as[(kA + 1) * 132 + mA + 64] = ra1.y;
            as[(kA + 2) * 132 + mA + 64] = ra1.z; as[(kA + 3) * 132 + mA + 64] = ra1.w;
            *(float4*)(bs + kB * 128 + nB) = rb0;
            *(float4*)(bs + (kB + 8) * 128 + nB) = rb1;
        }
        __syncthreads();
        p ^= 1;
    }
    {
        const float* as = As[p]; const float* bs = Bs[p];
#pragma unroll
        for (int kk = 0; kk < 16; ++kk) {
            float a[8], b[8];
            *(float4*)(a)     = *(const float4*)(as + kk * 132 + ty * 8);
            *(float4*)(a + 4) = *(const float4*)(as + kk * 132 + ty * 8 + 4);
            *(float4*)(b)     = *(const float4*)(bs + kk * 128 + tx * 8);
            *(float4*)(b + 4) = *(const float4*)(bs + kk * 128 + tx * 8 + 4);
#pragma unroll
            for (int r = 0; r < 8; ++r)
#pragma unroll
                for (int c = 0; c < 8; ++c)
                    acc[r][c] = fmaf(a[r], b[c], acc[r][c]);
        }
    }

#pragma unroll
    for (int c = 0; c < 8; ++c) {
        int col = col0 + tx * 8 + c;          // col = h*192 + d*3 + sel
        int h = col / 192;
        int rem = col - h * 192;
        int d = rem / 3;
        int sel = rem - d * 3;
        float* dst = (sel == 0) ? g_q : (sel == 1) ? g_k : g_v;
#pragma unroll
        for (int r = 0; r < 8; ++r) {
            int row = row0 + ty * 8 + r;
            int bidx = row >> 13, n = row & 8191;
            dst[((size_t)(bidx * 12 + h) * 8192 + n) * 64 + d] = acc[r][c];
        }
    }
}

// ---------------- fused windowed attention (512 threads) ----------------
// grid: (qt=4, w=32, bh=24); block 512
// smem: sG 20544f (relK [d][u] / G [ii][u] str321 -> Pt [j][i] str66)
//       sK 17408f (K [d][j] str260 -> V [j][d] str68)
//       sQc 4352f, sQp 4352f ([d][i] str68). total 46656 f = 186624 B
#define ATTN_SMEM_FLOATS 46656
__global__ __launch_bounds__(512, 1) void attn_kernel(
    const float* __restrict__ RK,
    const float* __restrict__ rcb,
    const float* __restrict__ rpb)
{
    extern __shared__ float sm[];
    float* sG  = sm;
    float* sK  = sm + 20544;
    float* sQc = sm + 20544 + 17408;
    float* sQp = sQc + 4352;

    int qt = blockIdx.x, w = blockIdx.y, bh = blockIdx.z;
    int bb = bh / 12;
    int h = bh - bb * 12;
    int tid = threadIdx.x;

    const float* qbase = g_q + ((size_t)bh * 8192 + w * 256 + qt * 64) * 64;
    const float* kbase = g_k + ((size_t)bh * 8192 + w * 256) * 64;
    const float* vbase = g_v + ((size_t)bh * 8192 + w * 256) * 64;

    // ---- stage Qc/Qp, K, relK slab ----
#pragma unroll
    for (int it = 0; it < 2; ++it) {
        int e = (it * 512 + tid) * 4;
        int ii = e >> 6, d = e & 63;
        float4 qv = *(const float4*)(qbase + ii * 64 + d);
        float4 cb = *(const float4*)(rcb + h * 64 + d);
        float4 pb = *(const float4*)(rpb + h * 64 + d);
        sQc[(d + 0) * 68 + ii] = (qv.x + cb.x) * 0.125f;
        sQc[(d + 1) * 68 + ii] = (qv.y + cb.y) * 0.125f;
        sQc[(d + 2) * 68 + ii] = (qv.z + cb.z) * 0.125f;
        sQc[(d + 3) * 68 + ii] = (qv.w + cb.w) * 0.125f;
        sQp[(d + 0) * 68 + ii] = qv.x + pb.x;
        sQp[(d + 1) * 68 + ii] = qv.y + pb.y;
        sQp[(d + 2) * 68 + ii] = qv.z + pb.z;
        sQp[(d + 3) * 68 + ii] = qv.w + pb.w;
    }
#pragma unroll
    for (int it = 0; it < 8; ++it) {
        int e = (it * 512 + tid) * 4;
        int j = e >> 6, d = e & 63;
        float4 kv = *(const float4*)(kbase + j * 64 + d);
        sK[(d + 0) * 260 + j] = kv.x;
        sK[(d + 1) * 260 + j] = kv.y;
        sK[(d + 2) * 260 + j] = kv.z;
        sK[(d + 3) * 260 + j] = kv.w;
    }
    int base_rel = 192 - qt * 64;
    const float* RKh = RK + h * 64;
#pragma unroll
    for (int it = 0; it < 10; ++it) {
        int e = (it * 512 + tid) * 4;
        int u = e >> 6, d = e & 63;
        int idx = base_rel + u;
        float4 rv = make_float4(0.f, 0.f, 0.f, 0.f);
        if (idx < 511) rv = *(const float4*)(RKh + (size_t)idx * 768 + d);
        sG[(d + 0) * 321 + u] = rv.x;
        sG[(d + 1) * 321 + u] = rv.y;
        sG[(d + 2) * 321 + u] = rv.z;
        sG[(d + 3) * 321 + u] = rv.w;
    }
    __syncthreads();

    // ---- phase G: G[ii][u] = Qp . relK_slab  (64 x 320 x 64) ----
    {
        int gy = tid >> 5, gx = tid & 31;    // gy 0..15 (4 rows each), gx: 5+5 cols
        float accG[4][10] = {};
        for (int d = 0; d < 64; ++d) {
            float a[4];
            *(float4*)(a) = *(float4*)(sQp + d * 68 + gy * 4);
            float bv[10];
#pragma unroll
            for (int c = 0; c < 5; ++c) {
                bv[c]     = sG[d * 321 + gx * 5 + c];
                bv[5 + c] = sG[d * 321 + 160 + gx * 5 + c];
            }
#pragma unroll
            for (int r = 0; r < 4; ++r)
#pragma unroll
                for (int c = 0; c < 10; ++c)
                    accG[r][c] = fmaf(a[r], bv[c], accG[r][c]);
        }
        __syncthreads();   // all reads of relK slab done
#pragma unroll
        for (int r = 0; r < 4; ++r)
#pragma unroll
            for (int c = 0; c < 5; ++c) {
                sG[(gy * 4 + r) * 321 + gx * 5 + c]       = accG[r][c];
                sG[(gy * 4 + r) * 321 + 160 + gx * 5 + c] = accG[r][5 + c];
            }
    }
    __syncthreads();

    // ---- phase S: scores = Qc . K^T + gather(G), softmax (intra-warp) ----
    int ty = tid >> 5, tx = tid & 31;   // 16 warps x 4 rows; lanes: cols tx*4 & 128+tx*4
    float acc[4][8] = {};
    for (int d = 0; d < 64; ++d) {
        float a[4], b[8];
        *(float4*)(a)     = *(float4*)(sQc + d * 68 + ty * 4);
        *(float4*)(b)     = *(float4*)(sK + d * 260 + tx * 4);
        *(float4*)(b + 4) = *(float4*)(sK + d * 260 + 128 + tx * 4);
#pragma unroll
        for (int r = 0; r < 4; ++r)
#pragma unroll
            for (int c = 0; c < 8; ++c)
                acc[r][c] = fmaf(a[r], b[c], acc[r][c]);
    }
#pragma unroll
    for (int r = 0; r < 4; ++r) {
        int ii = ty * 4 + r;
        const float* grow = sG + ii * 321 + 63 - ii;   // u = j - ii + 63
#pragma unroll
        for (int c = 0; c < 4; ++c) {
            acc[r][c]     += grow[tx * 4 + c];
            acc[r][4 + c] += grow[128 + tx * 4 + c];
        }
    }
#pragma unroll
    for (int r = 0; r < 4; ++r) {
        float m = acc[r][0];
#pragma unroll
        for (int c = 1; c < 8; ++c) m = fmaxf(m, acc[r][c]);
#pragma unroll
        for (int off = 16; off > 0; off >>= 1)
            m = fmaxf(m, __shfl_xor_sync(0xffffffffu, m, off));
        float s = 0.f;
#pragma unroll
        for (int c = 0; c < 8; ++c) { acc[r][c] = expf(acc[r][c] - m); s += acc[r][c]; }
#pragma unroll
        for (int off = 16; off > 0; off >>= 1)
            s += __shfl_xor_sync(0xffffffffu, s, off);
        float inv = 1.0f / s;
#pragma unroll
        for (int c = 0; c < 8; ++c) acc[r][c] *= inv;
    }
    __syncthreads();  // all gather reads of G / K reads done

    // ---- phase AV: Pt into sG, V into sK, O = P . V ----
#pragma unroll
    for (int r = 0; r < 4; ++r)
#pragma unroll
        for (int c = 0; c < 4; ++c) {
            sG[(tx * 4 + c) * 66 + ty * 4 + r]       = acc[r][c];
            sG[(128 + tx * 4 + c) * 66 + ty * 4 + r] = acc[r][4 + c];
        }
#pragma unroll
    for (int it = 0; it < 8; ++it) {
        int e = (it * 512 + tid) * 4;
        int j = e >> 6, d = e & 63;
        *(float4*)(sK + j * 68 + d) = *(const float4*)(vbase + j * 64 + d);
    }
    __syncthreads();

    int oy = tid >> 4, ox = tid & 15;    // 32 row-pairs x 16 col-quads
    float o[2][4] = {};
#pragma unroll 4
    for (int j = 0; j < 256; ++j) {
        float2 pp = *(float2*)(sG + j * 66 + oy * 2);
        float4 bv4 = *(float4*)(sK + j * 68 + ox * 4);
        o[0][0] = fmaf(pp.x, bv4.x, o[0][0]); o[0][1] = fmaf(pp.x, bv4.y, o[0][1]);
        o[0][2] = fmaf(pp.x, bv4.z, o[0][2]); o[0][3] = fmaf(pp.x, bv4.w, o[0][3]);
        o[1][0] = fmaf(pp.y, bv4.x, o[1][0]); o[1][1] = fmaf(pp.y, bv4.y, o[1][1]);
        o[1][2] = fmaf(pp.y, bv4.z, o[1][2]); o[1][3] = fmaf(pp.y, bv4.w, o[1][3]);
    }
    float* out0 = g_attn + ((size_t)bb * 8192 + w * 256 + qt * 64) * 768 + h * 64;
#pragma unroll
    for (int r = 0; r < 2; ++r) {
        float4 ov = make_float4(o[r][0], o[r][1], o[r][2], o[r][3]);
        *(float4*)(out0 + (size_t)(oy * 2 + r) * 768 + ox * 4) = ov;
    }
}

// ---------------- launch ----------------
extern "C" void kernel_launch(void* const* d_in, const int* in_sizes, int n_in,
                              void* d_out, int out_size)
{
    const float* x    = (const float*)d_in[0];
    const float* wqkv = (const float*)d_in[1];
    const float* wout = (const float*)d_in[2];
    const float* bout = (const float*)d_in[3];
    const float* wrel = (const float*)d_in[4];
    const float* rcb  = (const float*)d_in[5];
    const float* rpb  = (const float*)d_in[6];
    float* out = (float*)d_out;

    float *P, *RK, *attn;
    cudaGetSymbolAddress((void**)&P,    g_P);
    cudaGetSymbolAddress((void**)&RK,   g_RK);
    cudaGetSymbolAddress((void**)&attn, g_attn);

    const int SMEM_BYTES = ATTN_SMEM_FLOATS * 4;  // 186624
    cudaFuncSetAttribute(attn_kernel,
                         cudaFuncAttributeMaxDynamicSharedMemorySize, SMEM_BYTES);

    // 1) positional embedding
    pos_kernel<<<511, 128>>>(P);
    // 2) rel_k = P @ w_rel   (511 x 768 x 768)
    gemm_bias_kernel<<<dim3(6, 4), 256>>>(P, wrel, RK, nullptr, 511, 768, 768);
    // 3) qkv projection with scatter to (B,H,N,D)
    gemm_qkv_kernel<<<dim3(18, 128), 256>>>(x, wqkv);
    // 4) fused windowed attention
    attn_kernel<<<dim3(4, 32, 24), 512, SMEM_BYTES>>>(RK, rcb, rpb);
    // 5) output projection + bias
    gemm_bias_kernel<<<dim3(6, 128), 256>>>(attn, wout, out, bout, 16384, 768, 768);
}

// round 15
// speedup vs baseline: 1.5575x; 1.4424x over previous
#include <cuda_runtime.h>
#include <cuda_bf16.h>
#include <stdint.h>
#include <math.h>

// ---------------- scratch (device globals; no allocation allowed) ----------------
__device__ __align__(16) float g_q[2 * 12 * 8192 * 64];
__device__ __align__(16) float g_k[2 * 12 * 8192 * 64];
__device__ __align__(16) float g_v[2 * 12 * 8192 * 64];
__device__ __align__(16) float g_attn[16384 * 768];
__device__ __align__(16) float g_P[511 * 768];
__device__ __align__(16) float g_RK[511 * 768];
// split-bf16 operands
__device__ __align__(16) __nv_bfloat16 g_xh[16384 * 768];
__device__ __align__(16) __nv_bfloat16 g_xl[16384 * 768];
__device__ __align__(16) __nv_bfloat16 g_wqh[2304 * 768];   // transposed [N][K]
__device__ __align__(16) __nv_bfloat16 g_wql[2304 * 768];
__device__ __align__(16) __nv_bfloat16 g_woh[768 * 768];    // transposed [N][K]
__device__ __align__(16) __nv_bfloat16 g_wol[768 * 768];
__device__ __align__(16) __nv_bfloat16 g_ah[16384 * 768];
__device__ __align__(16) __nv_bfloat16 g_al[16384 * 768];

// ---------------- warp-MMA helpers (base-PTX; no sm_103a-only instructions) ----
__device__ __forceinline__ uint32_t smem_u32(const void* p) {
    uint32_t a;
    asm("{ .reg .u64 t; cvta.to.shared.u64 t, %1; cvt.u32.u64 %0, t; }" : "=r"(a) : "l"(p));
    return a;
}
__device__ __forceinline__ void ldsm4(uint32_t* r, uint32_t a) {
    asm volatile("ldmatrix.sync.aligned.m8n8.x4.shared.b16 {%0,%1,%2,%3}, [%4];"
        : "=r"(r[0]), "=r"(r[1]), "=r"(r[2]), "=r"(r[3]) : "r"(a));
}
__device__ __forceinline__ void ldsm2(uint32_t* r, uint32_t a) {
    asm volatile("ldmatrix.sync.aligned.m8n8.x2.shared.b16 {%0,%1}, [%2];"
        : "=r"(r[0]), "=r"(r[1]) : "r"(a));
}
__device__ __forceinline__ void mma_bf16(float* d, const uint32_t* a, const uint32_t* b) {
    asm volatile("mma.sync.aligned.m16n8k16.row.col.f32.bf16.bf16.f32 "
        "{%0,%1,%2,%3}, {%4,%5,%6,%7}, {%8,%9}, {%0,%1,%2,%3};"
        : "+f"(d[0]), "+f"(d[1]), "+f"(d[2]), "+f"(d[3])
        : "r"(a[0]), "r"(a[1]), "r"(a[2]), "r"(a[3]), "r"(b[0]), "r"(b[1]));
}

// ---------------- positional embedding (511 x 768) ----------------
__global__ void pos_kernel(float* __restrict__ P) {
    int row = blockIdx.x;
    int f = threadIdx.x;
    float dist = (float)(row - 255);
    float absd = fabsf(dist);

    float hl = exp2f(3.0f + (float)f * (5.0f / 127.0f));
    float fe = expf(-(0.6931471805599453f / hl) * absd);
    float cw = exp2f((float)(f + 1)) - 1.0f;
    float fc = (cw > absd) ? 1.0f : 0.0f;
    double mean = 2.0 + 2.0 * (double)f;
    double conc = mean * mean;
    double lu;
    if (absd > 0.0f) lu = (conc - 1.0) * log((double)absd) - mean * (double)absd;
    else             lu = -INFINITY;
    double lnorm = lgamma(conc) - conc * log(mean);
    double prob = exp(lu - lnorm) + 1e-8;

    __shared__ double red[128];
    red[f] = prob;
    __syncthreads();
    for (int s = 64; s > 0; s >>= 1) {
        if (f < s) red[f] = fmax(red[f], red[f + s]);
        __syncthreads();
    }
    double mp = red[0];
    float fg = (float)(prob / mp);

    float sgn = (dist > 0.f) ? 1.f : ((dist < 0.f) ? -1.f : 0.f);
    float* Pr = P + (size_t)row * 768;
    Pr[f]       = fe;  Pr[128 + f] = fc;        Pr[256 + f] = fg;
    Pr[384 + f] = sgn * fe; Pr[512 + f] = sgn * fc; Pr[640 + f] = sgn * fg;
}

// ---------------- generic fp32 SIMT GEMM (relk only: 511x768x768) ----------------
__global__ __launch_bounds__(256, 2) void gemm_bias_kernel(
    const float* __restrict__ A, const float* __restrict__ B,
    float* __restrict__ C, const float* __restrict__ bias,
    int M, int N, int K)
{
    __shared__ float As[2][16 * 132];
    __shared__ float Bs[2][16 * 128];
    int tid = threadIdx.x;
    int ty = tid >> 4, tx = tid & 15;
    int row0 = blockIdx.y * 128, col0 = blockIdx.x * 128;
    float acc[8][8] = {};

    int mA = tid >> 2, kA = (tid & 3) * 4;
    int kB = tid >> 5, nB = (tid & 31) * 4;

    const float* Ap0 = A + (size_t)(row0 + mA) * K + kA;
    const float* Ap1 = Ap0 + (size_t)64 * K;
    const float* Bp0 = B + (size_t)kB * N + col0 + nB;
    const float* Bp1 = Bp0 + (size_t)8 * N;
    bool ga0 = (row0 + mA) < M;
    bool ga1 = (row0 + mA + 64) < M;
    const float4 z4 = make_float4(0.f, 0.f, 0.f, 0.f);

    float4 ra0 = ga0 ? *(const float4*)(Ap0) : z4;
    float4 ra1 = ga1 ? *(const float4*)(Ap1) : z4;
    float4 rb0 = *(const float4*)(Bp0);
    float4 rb1 = *(const float4*)(Bp1);
    int p = 0;
    {
        float* as = As[0]; float* bs = Bs[0];
        as[(kA + 0) * 132 + mA] = ra0.x; as[(kA + 1) * 132 + mA] = ra0.y;
        as[(kA + 2) * 132 + mA] = ra0.z; as[(kA + 3) * 132 + mA] = ra0.w;
        as[(kA + 0) * 132 + mA + 64] = ra1.x; as[(kA + 1) * 132 + mA + 64] = ra1.y;
        as[(kA + 2) * 132 + mA + 64] = ra1.z; as[(kA + 3) * 132 + mA + 64] = ra1.w;
        *(float4*)(bs + kB * 128 + nB) = rb0;
        *(float4*)(bs + (kB + 8) * 128 + nB) = rb1;
    }
    __syncthreads();

    for (int kt = 16; kt < K; kt += 16) {
        ra0 = ga0 ? *(const float4*)(Ap0 + kt) : z4;
        ra1 = ga1 ? *(const float4*)(Ap1 + kt) : z4;
        rb0 = *(const float4*)(Bp0 + (size_t)kt * N);
        rb1 = *(const float4*)(Bp1 + (size_t)kt * N);
        {
            const float* as = As[p]; const float* bs = Bs[p];
#pragma unroll
            for (int kk = 0; kk < 16; ++kk) {
                float a[8], b[8];
                *(float4*)(a)     = *(const float4*)(as + kk * 132 + ty * 8);
                *(float4*)(a + 4) = *(const float4*)(as + kk * 132 + ty * 8 + 4);
                *(float4*)(b)     = *(const float4*)(bs + kk * 128 + tx * 8);
                *(float4*)(b + 4) = *(const float4*)(bs + kk * 128 + tx * 8 + 4);
#pragma unroll
                for (int r = 0; r < 8; ++r)
#pragma unroll
                    for (int c = 0; c < 8; ++c)
                        acc[r][c] = fmaf(a[r], b[c], acc[r][c]);
            }
        }
        {
            float* as = As[p ^ 1]; float* bs = Bs[p ^ 1];
            as[(kA + 0) * 132 + mA] = ra0.x; as[(kA + 1) * 132 + mA] = ra0.y;
            as[(kA + 2) * 132 + mA] = ra0.z; as[(kA + 3) * 132 + mA] = ra0.w;
            as[(kA + 0) * 132 + mA + 64] = ra1.x; as[(kA + 1) * 132 + mA + 64] = ra1.y;
            as[(kA + 2) * 132 + mA + 64] = ra1.z; as[(kA + 3) * 132 + mA + 64] = ra1.w;
            *(float4*)(bs + kB * 128 + nB) = rb0;
            *(float4*)(bs + (kB + 8) * 128 + nB) = rb1;
        }
        __syncthreads();
        p ^= 1;
    }
    {
        const float* as = As[p]; const float* bs = Bs[p];
#pragma unroll
        for (int kk = 0; kk < 16; ++kk) {
            float a[8], b[8];
            *(float4*)(a)     = *(const float4*)(as + kk * 132 + ty * 8);
            *(float4*)(a + 4) = *(const float4*)(as + kk * 132 + ty * 8 + 4);
            *(float4*)(b)     = *(const float4*)(bs + kk * 128 + tx * 8);
            *(float4*)(b + 4) = *(const float4*)(bs + kk * 128 + tx * 8 + 4);
#pragma unroll
            for (int r = 0; r < 8; ++r)
#pragma unroll
                for (int c = 0; c < 8; ++c)
                    acc[r][c] = fmaf(a[r], b[c], acc[r][c]);
        }
    }

    float bb[8] = {};
    if (bias) {
#pragma unroll
        for (int c = 0; c < 8; ++c) bb[c] = bias[col0 + tx * 8 + c];
    }
#pragma unroll
    for (int r = 0; r < 8; ++r) {
        int row = row0 + ty * 8 + r;
        if (row < M) {
#pragma unroll
            for (int c = 0; c < 8; ++c)
                C[(size_t)row * N + col0 + tx * 8 + c] = acc[r][c] + bb[c];
        }
    }
}

// ---------------- fp32 -> (hi, lo) bf16 split, elementwise ----------------
__global__ __launch_bounds__(256) void conv_split(
    const float* __restrict__ in, __nv_bfloat16* __restrict__ oh,
    __nv_bfloat16* __restrict__ ol, int n)
{
    int i = (blockIdx.x * 256 + threadIdx.x) * 4;
    if (i >= n) return;
    float4 v = *(const float4*)(in + i);
    __nv_bfloat16 h0 = __float2bfloat16(v.x), h1 = __float2bfloat16(v.y);
    __nv_bfloat16 h2 = __float2bfloat16(v.z), h3 = __float2bfloat16(v.w);
    __nv_bfloat16 l0 = __float2bfloat16(v.x - __bfloat162float(h0));
    __nv_bfloat16 l1 = __float2bfloat16(v.y - __bfloat162float(h1));
    __nv_bfloat16 l2 = __float2bfloat16(v.z - __bfloat162float(h2));
    __nv_bfloat16 l3 = __float2bfloat16(v.w - __bfloat162float(h3));
    __nv_bfloat162 hp0 = {h0, h1}, hp1 = {h2, h3}, lp0 = {l0, l1}, lp1 = {l2, l3};
    *(__nv_bfloat162*)(oh + i)     = hp0;
    *(__nv_bfloat162*)(oh + i + 2) = hp1;
    *(__nv_bfloat162*)(ol + i)     = lp0;
    *(__nv_bfloat162*)(ol + i + 2) = lp1;
}

// ---------------- fp32 [K][N] -> transposed (hi, lo) bf16 [N][K] ----------------
__global__ __launch_bounds__(256) void conv_split_T(
    const float* __restrict__ in, __nv_bfloat16* __restrict__ oh,
    __nv_bfloat16* __restrict__ ol, int K, int N)
{
    __shared__ float t[32][33];
    int n0 = blockIdx.x * 32, k0 = blockIdx.y * 32;
    int tx = threadIdx.x, ty = threadIdx.y;    // block (32, 8)
#pragma unroll
    for (int r = 0; r < 4; ++r)
        t[ty + r * 8][tx] = in[(size_t)(k0 + ty + r * 8) * N + n0 + tx];
    __syncthreads();
#pragma unroll
    for (int r = 0; r < 4; ++r) {
        int nn = ty + r * 8;
        float v = t[tx][nn];
        __nv_bfloat16 h = __float2bfloat16(v);
        __nv_bfloat16 l = __float2bfloat16(v - __bfloat162float(h));
        size_t idx = (size_t)(n0 + nn) * K + k0 + tx;
        oh[idx] = h;
        ol[idx] = l;
    }
}

// ---------------- mma.sync split-bf16 GEMM: D = A(fp32~hi+lo) * B^T ----------------
// A: [M][K] bf16 hi/lo. B: [N][K] bf16 hi/lo. Tile 128x128, K-chunks of 64.
// MODE 0: scatter into g_q/g_k/g_v.  MODE 1: +bias -> C row-major.
#define MM_STRIDE 144          // bytes per smem row (64 bf16 data + 8 pad)
#define SM_AH 0
#define SM_AL 18432
#define SM_BH 36864
#define SM_BL 55296
#define MM_BYTES 73728
template <int MODE>
__global__ __launch_bounds__(256, 1) void mma_gemm(
    const __nv_bfloat16* __restrict__ Ah, const __nv_bfloat16* __restrict__ Al,
    const __nv_bfloat16* __restrict__ Bh, const __nv_bfloat16* __restrict__ Bl,
    int K, const float* __restrict__ bias, float* __restrict__ C, int ldc)
{
    extern __shared__ __align__(16) char smem[];
    uint32_t sb = smem_u32(smem);
    int tid = threadIdx.x, lane = tid & 31, wid = tid >> 5;
    int wm = wid & 3, wn = wid >> 2;        // warp tile: rows wm*32, cols wn*64
    int m0 = blockIdx.y * 128, n0 = blockIdx.x * 128;
    float acc[2][8][4] = {};

    // ldmatrix per-lane address pieces
    int aRow  = (lane & 7) + ((lane >> 3) & 1) * 8;   // x4: sub&1 -> +8 rows
    int aColB = ((lane >> 4) & 1) * 16;               // x4: sub>>1 -> +8 elems (16 B)
    int bRow  = lane & 7;                              // x2: lanes 0..15 used
    int bColB = ((lane >> 3) & 1) * 16;

    for (int kc = 0; kc < K; kc += 64) {
#pragma unroll
        for (int i = 0; i < 4; ++i) {
            int g = tid + i * 256;            // 0..1023
            int row = g >> 3, c = g & 7;
            uint32_t doff = (uint32_t)row * MM_STRIDE + c * 16;
            size_t asrc = (size_t)(m0 + row) * K + kc + c * 8;
            size_t bsrc = (size_t)(n0 + row) * K + kc + c * 8;
            *(uint4*)(smem + SM_AH + doff) = *(const uint4*)(Ah + asrc);
            *(uint4*)(smem + SM_AL + doff) = *(const uint4*)(Al + asrc);
            *(uint4*)(smem + SM_BH + doff) = *(const uint4*)(Bh + bsrc);
            *(uint4*)(smem + SM_BL + doff) = *(const uint4*)(Bl + bsrc);
        }
        __syncthreads();
#pragma unroll
        for (int ks = 0; ks < 4; ++ks) {
            uint32_t ah[2][4], al[2][4];
#pragma unroll
            for (int mt = 0; mt < 2; ++mt) {
                uint32_t ra = (uint32_t)(wm * 32 + mt * 16 + aRow) * MM_STRIDE + ks * 32 + aColB;
                ldsm4(ah[mt], sb + SM_AH + ra);
                ldsm4(al[mt], sb + SM_AL + ra);
            }
#pragma unroll
            for (int nt = 0; nt < 8; ++nt) {
                uint32_t rb = (uint32_t)(wn * 64 + nt * 8 + bRow) * MM_STRIDE + ks * 32 + bColB;
                uint32_t bh[2], bl[2];
                ldsm2(bh, sb + SM_BH + rb);
                ldsm2(bl, sb + SM_BL + rb);
#pragma unroll
                for (int mt = 0; mt < 2; ++mt) {
                    mma_bf16(acc[mt][nt], ah[mt], bh);
                    mma_bf16(acc[mt][nt], ah[mt], bl);
                    mma_bf16(acc[mt][nt], al[mt], bh);
                }
            }
        }
        __syncthreads();
    }

    int rbase = m0 + wm * 32 + (lane >> 2);
    int cbase = n0 + wn * 64 + (lane & 3) * 2;
    if (MODE == 0) {
#pragma unroll
        for (int mt = 0; mt < 2; ++mt)
#pragma unroll
            for (int nt = 0; nt < 8; ++nt)
#pragma unroll
                for (int dd = 0; dd < 2; ++dd) {
                    int row = rbase + mt * 16 + dd * 8;
                    int bidx = row >> 13, n = row & 8191;
#pragma unroll
                    for (int jj = 0; jj < 2; ++jj) {
                        int col = cbase + nt * 8 + jj;     // col = h*192 + d*3 + sel
                        int h = col / 192;
                        int rem = col - h * 192;
                        int d = rem / 3;
                        int sel = rem - d * 3;
                        float* dst = (sel == 0) ? g_q : (sel == 1) ? g_k : g_v;
                        dst[((size_t)(bidx * 12 + h) * 8192 + n) * 64 + d] =
                            acc[mt][nt][dd * 2 + jj];
                    }
                }
    } else {
#pragma unroll
        for (int mt = 0; mt < 2; ++mt)
#pragma unroll
            for (int nt = 0; nt < 8; ++nt)
#pragma unroll
                for (int dd = 0; dd < 2; ++dd) {
                    int row = rbase + mt * 16 + dd * 8;
                    int col = cbase + nt * 8;
                    float2 v;
                    v.x = acc[mt][nt][dd * 2 + 0] + bias[col];
                    v.y = acc[mt][nt][dd * 2 + 1] + bias[col + 1];
                    *(float2*)(C + (size_t)row * ldc + col) = v;
                }
    }
}

// ---------------- fused windowed attention (512 threads) ----------------
#define ATTN_SMEM_FLOATS 46656
__global__ __launch_bounds__(512, 1) void attn_kernel(
    const float* __restrict__ RK,
    const float* __restrict__ rcb,
    const float* __restrict__ rpb)
{
    extern __shared__ float sm[];
    float* sG  = sm;
    float* sK  = sm + 20544;
    float* sQc = sm + 20544 + 17408;
    float* sQp = sQc + 4352;

    int qt = blockIdx.x, w = blockIdx.y, bh = blockIdx.z;
    int bb = bh / 12;
    int h = bh - bb * 12;
    int tid = threadIdx.x;

    const float* qbase = g_q + ((size_t)bh * 8192 + w * 256 + qt * 64) * 64;
    const float* kbase = g_k + ((size_t)bh * 8192 + w * 256) * 64;
    const float* vbase = g_v + ((size_t)bh * 8192 + w * 256) * 64;

#pragma unroll
    for (int it = 0; it < 2; ++it) {
        int e = (it * 512 + tid) * 4;
        int ii = e >> 6, d = e & 63;
        float4 qv = *(const float4*)(qbase + ii * 64 + d);
        float4 cb = *(const float4*)(rcb + h * 64 + d);
        float4 pb = *(const float4*)(rpb + h * 64 + d);
        sQc[(d + 0) * 68 + ii] = (qv.x + cb.x) * 0.125f;
        sQc[(d + 1) * 68 + ii] = (qv.y + cb.y) * 0.125f;
        sQc[(d + 2) * 68 + ii] = (qv.z + cb.z) * 0.125f;
        sQc[(d + 3) * 68 + ii] = (qv.w + cb.w) * 0.125f;
        sQp[(d + 0) * 68 + ii] = qv.x + pb.x;
        sQp[(d + 1) * 68 + ii] = qv.y + pb.y;
        sQp[(d + 2) * 68 + ii] = qv.z + pb.z;
        sQp[(d + 3) * 68 + ii] = qv.w + pb.w;
    }
#pragma unroll
    for (int it = 0; it < 8; ++it) {
        int e = (it * 512 + tid) * 4;
        int j = e >> 6, d = e & 63;
        float4 kv = *(const float4*)(kbase + j * 64 + d);
        sK[(d + 0) * 260 + j] = kv.x;
        sK[(d + 1) * 260 + j] = kv.y;
        sK[(d + 2) * 260 + j] = kv.z;
        sK[(d + 3) * 260 + j] = kv.w;
    }
    int base_rel = 192 - qt * 64;
    const float* RKh = RK + h * 64;
#pragma unroll
    for (int it = 0; it < 10; ++it) {
        int e = (it * 512 + tid) * 4;
        int u = e >> 6, d = e & 63;
        int idx = base_rel + u;
        float4 rv = make_float4(0.f, 0.f, 0.f, 0.f);
        if (idx < 511) rv = *(const float4*)(RKh + (size_t)idx * 768 + d);
        sG[(d + 0) * 321 + u] = rv.x;
        sG[(d + 1) * 321 + u] = rv.y;
        sG[(d + 2) * 321 + u] = rv.z;
        sG[(d + 3) * 321 + u] = rv.w;
    }
    __syncthreads();

    {
        int gy = tid >> 5, gx = tid & 31;
        float accG[4][10] = {};
        for (int d = 0; d < 64; ++d) {
            float a[4];
            *(float4*)(a) = *(float4*)(sQp + d * 68 + gy * 4);
            float bv[10];
#pragma unroll
            for (int c = 0; c < 5; ++c) {
                bv[c]     = sG[d * 321 + gx * 5 + c];
                bv[5 + c] = sG[d * 321 + 160 + gx * 5 + c];
            }
#pragma unroll
            for (int r = 0; r < 4; ++r)
#pragma unroll
                for (int c = 0; c < 10; ++c)
                    accG[r][c] = fmaf(a[r], bv[c], accG[r][c]);
        }
        __syncthreads();
#pragma unroll
        for (int r = 0; r < 4; ++r)
#pragma unroll
            for (int c = 0; c < 5; ++c) {
                sG[(gy * 4 + r) * 321 + gx * 5 + c]       = accG[r][c];
                sG[(gy * 4 + r) * 321 + 160 + gx * 5 + c] = accG[r][5 + c];
            }
    }
    __syncthreads();

    int ty = tid >> 5, tx = tid & 31;
    float acc[4][8] = {};
    for (int d = 0; d < 64; ++d) {
        float a[4], b[8];
        *(float4*)(a)     = *(float4*)(sQc + d * 68 + ty * 4);
        *(float4*)(b)     = *(float4*)(sK + d * 260 + tx * 4);
        *(float4*)(b + 4) = *(float4*)(sK + d * 260 + 128 + tx * 4);
#pragma unroll
        for (int r = 0; r < 4; ++r)
#pragma unroll
            for (int c = 0; c < 8; ++c)
                acc[r][c] = fmaf(a[r], b[c], acc[r][c]);
    }
#pragma unroll
    for (int r = 0; r < 4; ++r) {
        int ii = ty * 4 + r;
        const float* grow = sG + ii * 321 + 63 - ii;
#pragma unroll
        for (int c = 0; c < 4; ++c) {
            acc[r][c]     += grow[tx * 4 + c];
            acc[r][4 + c] += grow[128 + tx * 4 + c];
        }
    }
#pragma unroll
    for (int r = 0; r < 4; ++r) {
        float m = acc[r][0];
#pragma unroll
        for (int c = 1; c < 8; ++c) m = fmaxf(m, acc[r][c]);
#pragma unroll
        for (int off = 16; off > 0; off >>= 1)
            m = fmaxf(m, __shfl_xor_sync(0xffffffffu, m, off));
        float s = 0.f;
#pragma unroll
        for (int c = 0; c < 8; ++c) { acc[r][c] = expf(acc[r][c] - m); s += acc[r][c]; }
#pragma unroll
        for (int off = 16; off > 0; off >>= 1)
            s += __shfl_xor_sync(0xffffffffu, s, off);
        float inv = 1.0f / s;
#pragma unroll
        for (int c = 0; c < 8; ++c) acc[r][c] *= inv;
    }
    __syncthreads();

#pragma unroll
    for (int r = 0; r < 4; ++r)
#pragma unroll
        for (int c = 0; c < 4; ++c) {
            sG[(tx * 4 + c) * 66 + ty * 4 + r]       = acc[r][c];
            sG[(128 + tx * 4 + c) * 66 + ty * 4 + r] = acc[r][4 + c];
        }
#pragma unroll
    for (int it = 0; it < 8; ++it) {
        int e = (it * 512 + tid) * 4;
        int j = e >> 6, d = e & 63;
        *(float4*)(sK + j * 68 + d) = *(const float4*)(vbase + j * 64 + d);
    }
    __syncthreads();

    int oy = tid >> 4, ox = tid & 15;
    float o[2][4] = {};
#pragma unroll 4
    for (int j = 0; j < 256; ++j) {
        float2 pp = *(float2*)(sG + j * 66 + oy * 2);
        float4 bv4 = *(float4*)(sK + j * 68 + ox * 4);
        o[0][0] = fmaf(pp.x, bv4.x, o[0][0]); o[0][1] = fmaf(pp.x, bv4.y, o[0][1]);
        o[0][2] = fmaf(pp.x, bv4.z, o[0][2]); o[0][3] = fmaf(pp.x, bv4.w, o[0][3]);
        o[1][0] = fmaf(pp.y, bv4.x, o[1][0]); o[1][1] = fmaf(pp.y, bv4.y, o[1][1]);
        o[1][2] = fmaf(pp.y, bv4.z, o[1][2]); o[1][3] = fmaf(pp.y, bv4.w, o[1][3]);
    }
    float* out0 = g_attn + ((size_t)bb * 8192 + w * 256 + qt * 64) * 768 + h * 64;
#pragma unroll
    for (int r = 0; r < 2; ++r) {
        float4 ov = make_float4(o[r][0], o[r][1], o[r][2], o[r][3]);
        *(float4*)(out0 + (size_t)(oy * 2 + r) * 768 + ox * 4) = ov;
    }
}

// ---------------- launch ----------------
extern "C" void kernel_launch(void* const* d_in, const int* in_sizes, int n_in,
                              void* d_out, int out_size)
{
    const float* x    = (const float*)d_in[0];
    const float* wqkv = (const float*)d_in[1];
    const float* wout = (const float*)d_in[2];
    const float* bout = (const float*)d_in[3];
    const float* wrel = (const float*)d_in[4];
    const float* rcb  = (const float*)d_in[5];
    const float* rpb  = (const float*)d_in[6];
    float* out = (float*)d_out;

    float *P, *RK, *attn;
    __nv_bfloat16 *xh, *xl, *wqh, *wql, *woh, *wol, *ah, *al;
    cudaGetSymbolAddress((void**)&P,    g_P);
    cudaGetSymbolAddress((void**)&RK,   g_RK);
    cudaGetSymbolAddress((void**)&attn, g_attn);
    cudaGetSymbolAddress((void**)&xh,  g_xh);
    cudaGetSymbolAddress((void**)&xl,  g_xl);
    cudaGetSymbolAddress((void**)&wqh, g_wqh);
    cudaGetSymbolAddress((void**)&wql, g_wql);
    cudaGetSymbolAddress((void**)&woh, g_woh);
    cudaGetSymbolAddress((void**)&wol, g_wol);
    cudaGetSymbolAddress((void**)&ah,  g_ah);
    cudaGetSymbolAddress((void**)&al,  g_al);

    const int ATTN_SMEM_BYTES = ATTN_SMEM_FLOATS * 4;
    cudaFuncSetAttribute(attn_kernel,
                         cudaFuncAttributeMaxDynamicSharedMemorySize, ATTN_SMEM_BYTES);
    cudaFuncSetAttribute(mma_gemm<0>,
                         cudaFuncAttributeMaxDynamicSharedMemorySize, MM_BYTES);
    cudaFuncSetAttribute(mma_gemm<1>,
                         cudaFuncAttributeMaxDynamicSharedMemorySize, MM_BYTES);

    // 1) positional embedding + rel_k (SIMT; small)
    pos_kernel<<<511, 128>>>(P);
    gemm_bias_kernel<<<dim3(6, 4), 256>>>(P, wrel, RK, nullptr, 511, 768, 768);

    // 2) split x and transpose-split w_qkv
    conv_split<<<16384 * 768 / 1024, 256>>>(x, xh, xl, 16384 * 768);
    conv_split_T<<<dim3(2304 / 32, 768 / 32), dim3(32, 8)>>>(wqkv, wqh, wql, 768, 2304);

    // 3) QKV projection on tensor cores (scatter epilogue)
    mma_gemm<0><<<dim3(18, 128), 256, MM_BYTES>>>(xh, xl, wqh, wql, 768,
                                                  nullptr, nullptr, 0);

    // 4) fused windowed attention
    attn_kernel<<<dim3(4, 32, 24), 512, ATTN_SMEM_BYTES>>>(RK, rcb, rpb);

    // 5) split attn output + transpose-split w_out; output projection on tensor cores
    conv_split<<<16384 * 768 / 1024, 256>>>(attn, ah, al, 16384 * 768);
    conv_split_T<<<dim3(768 / 32, 768 / 32), dim3(32, 8)>>>(wout, woh, wol, 768, 768);
    mma_gemm<1><<<dim3(6, 128), 256, MM_BYTES>>>(ah, al, woh, wol, 768,
                                                 bout, out, 768);
}

// round 16
// speedup vs baseline: 1.9150x; 1.2295x over previous
#include <cuda_runtime.h>
#include <cuda_bf16.h>
#include <stdint.h>
#include <math.h>

// ---------------- scratch (device globals; no allocation allowed) ----------------
__device__ __align__(16) float g_q[2 * 12 * 8192 * 64];
__device__ __align__(16) float g_attn[16384 * 768];
__device__ __align__(16) float g_P[511 * 768];
__device__ __align__(16) float g_RK[511 * 768];
// split-bf16 operands
__device__ __align__(16) __nv_bfloat16 g_xh[16384 * 768];
__device__ __align__(16) __nv_bfloat16 g_xl[16384 * 768];
__device__ __align__(16) __nv_bfloat16 g_wqh[2304 * 768];   // transposed [N][K]
__device__ __align__(16) __nv_bfloat16 g_wql[2304 * 768];
__device__ __align__(16) __nv_bfloat16 g_woh[768 * 768];    // transposed [N][K]
__device__ __align__(16) __nv_bfloat16 g_wol[768 * 768];
__device__ __align__(16) __nv_bfloat16 g_ah[16384 * 768];
__device__ __align__(16) __nv_bfloat16 g_al[16384 * 768];
// attention operands (split, produced by QKV epilogue)
__device__ __align__(16) __nv_bfloat16 g_kh[2 * 12 * 8192 * 64];   // [bh][n][d]
__device__ __align__(16) __nv_bfloat16 g_kl[2 * 12 * 8192 * 64];
__device__ __align__(16) __nv_bfloat16 g_vTh[2 * 12 * 64 * 8192];  // [bh][d][n]
__device__ __align__(16) __nv_bfloat16 g_vTl[2 * 12 * 64 * 8192];
__device__ __align__(16) __nv_bfloat16 g_RKh[511 * 768];
__device__ __align__(16) __nv_bfloat16 g_RKl[511 * 768];

// ---------------- warp-MMA helpers (base-PTX; validated in R15) ----------------
__device__ __forceinline__ uint32_t smem_u32(const void* p) {
    uint32_t a;
    asm("{ .reg .u64 t; cvta.to.shared.u64 t, %1; cvt.u32.u64 %0, t; }" : "=r"(a) : "l"(p));
    return a;
}
__device__ __forceinline__ void ldsm4(uint32_t* r, uint32_t a) {
    asm volatile("ldmatrix.sync.aligned.m8n8.x4.shared.b16 {%0,%1,%2,%3}, [%4];"
        : "=r"(r[0]), "=r"(r[1]), "=r"(r[2]), "=r"(r[3]) : "r"(a));
}
__device__ __forceinline__ void ldsm2(uint32_t* r, uint32_t a) {
    asm volatile("ldmatrix.sync.aligned.m8n8.x2.shared.b16 {%0,%1}, [%2];"
        : "=r"(r[0]), "=r"(r[1]) : "r"(a));
}
__device__ __forceinline__ void mma_bf16(float* d, const uint32_t* a, const uint32_t* b) {
    asm volatile("mma.sync.aligned.m16n8k16.row.col.f32.bf16.bf16.f32 "
        "{%0,%1,%2,%3}, {%4,%5,%6,%7}, {%8,%9}, {%0,%1,%2,%3};"
        : "+f"(d[0]), "+f"(d[1]), "+f"(d[2]), "+f"(d[3])
        : "r"(a[0]), "r"(a[1]), "r"(a[2]), "r"(a[3]), "r"(b[0]), "r"(b[1]));
}
__device__ __forceinline__ void split2(float v, __nv_bfloat16& hh, __nv_bfloat16& ll) {
    hh = __float2bfloat16(v);
    ll = __float2bfloat16(v - __bfloat162float(hh));
}

// ---------------- positional embedding (511 x 768) ----------------
__global__ void pos_kernel(float* __restrict__ P) {
    int row = blockIdx.x;
    int f = threadIdx.x;
    float dist = (float)(row - 255);
    float absd = fabsf(dist);

    float hl = exp2f(3.0f + (float)f * (5.0f / 127.0f));
    float fe = expf(-(0.6931471805599453f / hl) * absd);
    float cw = exp2f((float)(f + 1)) - 1.0f;
    float fc = (cw > absd) ? 1.0f : 0.0f;
    double mean = 2.0 + 2.0 * (double)f;
    double conc = mean * mean;
    double lu;
    if (absd > 0.0f) lu = (conc - 1.0) * log((double)absd) - mean * (double)absd;
    else             lu = -INFINITY;
    double lnorm = lgamma(conc) - conc * log(mean);
    double prob = exp(lu - lnorm) + 1e-8;

    __shared__ double red[128];
    red[f] = prob;
    __syncthreads();
    for (int s = 64; s > 0; s >>= 1) {
        if (f < s) red[f] = fmax(red[f], red[f + s]);
        __syncthreads();
    }
    double mp = red[0];
    float fg = (float)(prob / mp);

    float sgn = (dist > 0.f) ? 1.f : ((dist < 0.f) ? -1.f : 0.f);
    float* Pr = P + (size_t)row * 768;
    Pr[f]       = fe;  Pr[128 + f] = fc;        Pr[256 + f] = fg;
    Pr[384 + f] = sgn * fe; Pr[512 + f] = sgn * fc; Pr[640 + f] = sgn * fg;
}

// ---------------- generic fp32 SIMT GEMM (relk only: 511x768x768) ----------------
__global__ __launch_bounds__(256, 2) void gemm_bias_kernel(
    const float* __restrict__ A, const float* __restrict__ B,
    float* __restrict__ C, const float* __restrict__ bias,
    int M, int N, int K)
{
    __shared__ float As[2][16 * 132];
    __shared__ float Bs[2][16 * 128];
    int tid = threadIdx.x;
    int ty = tid >> 4, tx = tid & 15;
    int row0 = blockIdx.y * 128, col0 = blockIdx.x * 128;
    float acc[8][8] = {};

    int mA = tid >> 2, kA = (tid & 3) * 4;
    int kB = tid >> 5, nB = (tid & 31) * 4;

    const float* Ap0 = A + (size_t)(row0 + mA) * K + kA;
    const float* Ap1 = Ap0 + (size_t)64 * K;
    const float* Bp0 = B + (size_t)kB * N + col0 + nB;
    const float* Bp1 = Bp0 + (size_t)8 * N;
    bool ga0 = (row0 + mA) < M;
    bool ga1 = (row0 + mA + 64) < M;
    const float4 z4 = make_float4(0.f, 0.f, 0.f, 0.f);

    float4 ra0 = ga0 ? *(const float4*)(Ap0) : z4;
    float4 ra1 = ga1 ? *(const float4*)(Ap1) : z4;
    float4 rb0 = *(const float4*)(Bp0);
    float4 rb1 = *(const float4*)(Bp1);
    int p = 0;
    {
        float* as = As[0]; float* bs = Bs[0];
        as[(kA + 0) * 132 + mA] = ra0.x; as[(kA + 1) * 132 + mA] = ra0.y;
        as[(kA + 2) * 132 + mA] = ra0.z; as[(kA + 3) * 132 + mA] = ra0.w;
        as[(kA + 0) * 132 + mA + 64] = ra1.x; as[(kA + 1) * 132 + mA + 64] = ra1.y;
        as[(kA + 2) * 132 + mA + 64] = ra1.z; as[(kA + 3) * 132 + mA + 64] = ra1.w;
        *(float4*)(bs + kB * 128 + nB) = rb0;
        *(float4*)(bs + (kB + 8) * 128 + nB) = rb1;
    }
    __syncthreads();

    for (int kt = 16; kt < K; kt += 16) {
        ra0 = ga0 ? *(const float4*)(Ap0 + kt) : z4;
        ra1 = ga1 ? *(const float4*)(Ap1 + kt) : z4;
        rb0 = *(const float4*)(Bp0 + (size_t)kt * N);
        rb1 = *(const float4*)(Bp1 + (size_t)kt * N);
        {
            const float* as = As[p]; const float* bs = Bs[p];
#pragma unroll
            for (int kk = 0; kk < 16; ++kk) {
                float a[8], b[8];
                *(float4*)(a)     = *(const float4*)(as + kk * 132 + ty * 8);
                *(float4*)(a + 4) = *(const float4*)(as + kk * 132 + ty * 8 + 4);
                *(float4*)(b)     = *(const float4*)(bs + kk * 128 + tx * 8);
                *(float4*)(b + 4) = *(const float4*)(bs + kk * 128 + tx * 8 + 4);
#pragma unroll
                for (int r = 0; r < 8; ++r)
#pragma unroll
                    for (int c = 0; c < 8; ++c)
                        acc[r][c] = fmaf(a[r], b[c], acc[r][c]);
            }
        }
        {
            float* as = As[p ^ 1]; float* bs = Bs[p ^ 1];
            as[(kA + 0) * 132 + mA] = ra0.x; as[(kA + 1) * 132 + mA] = ra0.y;
            as[(kA + 2) * 132 + mA] = ra0.z; as[(kA + 3) * 132 + mA] = ra0.w;
            as[(kA + 0) * 132 + mA + 64] = ra1.x; as[(kA + 1) * 132 + mA + 64] = ra1.y;
            as[(kA + 2) * 132 + mA + 64] = ra1.z; as[(kA + 3) * 132 + mA + 64] = ra1.w;
            *(float4*)(bs + kB * 128 + nB) = rb0;
            *(float4*)(bs + (kB + 8) * 128 + nB) = rb1;
        }
        __syncthreads();
        p ^= 1;
    }
    {
        const float* as = As[p]; const float* bs = Bs[p];
#pragma unroll
        for (int kk = 0; kk < 16; ++kk) {
            float a[8], b[8];
            *(float4*)(a)     = *(const float4*)(as + kk * 132 + ty * 8);
            *(float4*)(a + 4) = *(const float4*)(as + kk * 132 + ty * 8 + 4);
            *(float4*)(b)     = *(const float4*)(bs + kk * 128 + tx * 8);
            *(float4*)(b + 4) = *(const float4*)(bs + kk * 128 + tx * 8 + 4);
#pragma unroll
            for (int r = 0; r < 8; ++r)
#pragma unroll
                for (int c = 0; c < 8; ++c)
                    acc[r][c] = fmaf(a[r], b[c], acc[r][c]);
        }
    }

    float bb[8] = {};
    if (bias) {
#pragma unroll
        for (int c = 0; c < 8; ++c) bb[c] = bias[col0 + tx * 8 + c];
    }
#pragma unroll
    for (int r = 0; r < 8; ++r) {
        int row = row0 + ty * 8 + r;
        if (row < M) {
#pragma unroll
            for (int c = 0; c < 8; ++c)
                C[(size_t)row * N + col0 + tx * 8 + c] = acc[r][c] + bb[c];
        }
    }
}

// ---------------- fp32 -> (hi, lo) bf16 split, elementwise ----------------
__global__ __launch_bounds__(256) void conv_split(
    const float* __restrict__ in, __nv_bfloat16* __restrict__ oh,
    __nv_bfloat16* __restrict__ ol, int n)
{
    int i = (blockIdx.x * 256 + threadIdx.x) * 4;
    if (i >= n) return;
    float4 v = *(const float4*)(in + i);
    __nv_bfloat16 h0, h1, h2, h3, l0, l1, l2, l3;
    split2(v.x, h0, l0); split2(v.y, h1, l1);
    split2(v.z, h2, l2); split2(v.w, h3, l3);
    __nv_bfloat162 hp0 = {h0, h1}, hp1 = {h2, h3}, lp0 = {l0, l1}, lp1 = {l2, l3};
    *(__nv_bfloat162*)(oh + i)     = hp0;
    *(__nv_bfloat162*)(oh + i + 2) = hp1;
    *(__nv_bfloat162*)(ol + i)     = lp0;
    *(__nv_bfloat162*)(ol + i + 2) = lp1;
}

// ---------------- fp32 [K][N] -> transposed (hi, lo) bf16 [N][K] ----------------
__global__ __launch_bounds__(256) void conv_split_T(
    const float* __restrict__ in, __nv_bfloat16* __restrict__ oh,
    __nv_bfloat16* __restrict__ ol, int K, int N)
{
    __shared__ float t[32][33];
    int n0 = blockIdx.x * 32, k0 = blockIdx.y * 32;
    int tx = threadIdx.x, ty = threadIdx.y;    // block (32, 8)
#pragma unroll
    for (int r = 0; r < 4; ++r)
        t[ty + r * 8][tx] = in[(size_t)(k0 + ty + r * 8) * N + n0 + tx];
    __syncthreads();
#pragma unroll
    for (int r = 0; r < 4; ++r) {
        int nn = ty + r * 8;
        float v = t[tx][nn];
        __nv_bfloat16 hh, ll;
        split2(v, hh, ll);
        size_t idx = (size_t)(n0 + nn) * K + k0 + tx;
        oh[idx] = hh;
        ol[idx] = ll;
    }
}

// ---------------- mma.sync split-bf16 GEMM: D = A(fp32~hi+lo) * B^T ----------------
#define MM_STRIDE 144
#define SM_AH 0
#define SM_AL 18432
#define SM_BH 36864
#define SM_BL 55296
#define MM_BYTES 73728
template <int MODE>
__global__ __launch_bounds__(256, 1) void mma_gemm(
    const __nv_bfloat16* __restrict__ Ah, const __nv_bfloat16* __restrict__ Al,
    const __nv_bfloat16* __restrict__ Bh, const __nv_bfloat16* __restrict__ Bl,
    int K, const float* __restrict__ bias, float* __restrict__ C, int ldc)
{
    extern __shared__ __align__(16) char smem[];
    uint32_t sb = smem_u32(smem);
    int tid = threadIdx.x, lane = tid & 31, wid = tid >> 5;
    int wm = wid & 3, wn = wid >> 2;
    int m0 = blockIdx.y * 128, n0 = blockIdx.x * 128;
    float acc[2][8][4] = {};

    int aRow  = (lane & 7) + ((lane >> 3) & 1) * 8;
    int aColB = ((lane >> 4) & 1) * 16;
    int bRow  = lane & 7;
    int bColB = ((lane >> 3) & 1) * 16;

    for (int kc = 0; kc < K; kc += 64) {
#pragma unroll
        for (int i = 0; i < 4; ++i) {
            int g = tid + i * 256;
            int row = g >> 3, c = g & 7;
            uint32_t doff = (uint32_t)row * MM_STRIDE + c * 16;
            size_t asrc = (size_t)(m0 + row) * K + kc + c * 8;
            size_t bsrc = (size_t)(n0 + row) * K + kc + c * 8;
            *(uint4*)(smem + SM_AH + doff) = *(const uint4*)(Ah + asrc);
            *(uint4*)(smem + SM_AL + doff) = *(const uint4*)(Al + asrc);
            *(uint4*)(smem + SM_BH + doff) = *(const uint4*)(Bh + bsrc);
            *(uint4*)(smem + SM_BL + doff) = *(const uint4*)(Bl + bsrc);
        }
        __syncthreads();
#pragma unroll
        for (int ks = 0; ks < 4; ++ks) {
            uint32_t ah[2][4], al[2][4];
#pragma unroll
            for (int mt = 0; mt < 2; ++mt) {
                uint32_t ra = (uint32_t)(wm * 32 + mt * 16 + aRow) * MM_STRIDE + ks * 32 + aColB;
                ldsm4(ah[mt], sb + SM_AH + ra);
                ldsm4(al[mt], sb + SM_AL + ra);
            }
#pragma unroll
            for (int nt = 0; nt < 8; ++nt) {
                uint32_t rb = (uint32_t)(wn * 64 + nt * 8 + bRow) * MM_STRIDE + ks * 32 + bColB;
                uint32_t bh[2], bl[2];
                ldsm2(bh, sb + SM_BH + rb);
                ldsm2(bl, sb + SM_BL + rb);
#pragma unroll
                for (int mt = 0; mt < 2; ++mt) {
                    mma_bf16(acc[mt][nt], ah[mt], bh);
                    mma_bf16(acc[mt][nt], ah[mt], bl);
                    mma_bf16(acc[mt][nt], al[mt], bh);
                }
            }
        }
        __syncthreads();
    }

    int rbase = m0 + wm * 32 + (lane >> 2);
    int cbase = n0 + wn * 64 + (lane & 3) * 2;
    if (MODE == 0) {
        // scatter: col = h*192 + d*3 + sel. q -> fp32; k -> bf16 hi/lo; v -> transposed bf16 hi/lo
#pragma unroll
        for (int mt = 0; mt < 2; ++mt)
#pragma unroll
            for (int nt = 0; nt < 8; ++nt)
#pragma unroll
                for (int dd = 0; dd < 2; ++dd) {
                    int row = rbase + mt * 16 + dd * 8;
                    int bidx = row >> 13, n = row & 8191;
#pragma unroll
                    for (int jj = 0; jj < 2; ++jj) {
                        int col = cbase + nt * 8 + jj;
                        int hh = col / 192;
                        int rem = col - hh * 192;
                        int d = rem / 3;
                        int sel = rem - d * 3;
                        int bh = bidx * 12 + hh;
                        float v = acc[mt][nt][dd * 2 + jj];
                        if (sel == 0) {
                            g_q[((size_t)bh * 8192 + n) * 64 + d] = v;
                        } else if (sel == 1) {
                            __nv_bfloat16 sh, sl;
                            split2(v, sh, sl);
                            size_t idx = ((size_t)bh * 8192 + n) * 64 + d;
                            g_kh[idx] = sh; g_kl[idx] = sl;
                        } else {
                            __nv_bfloat16 sh, sl;
                            split2(v, sh, sl);
                            size_t idx = ((size_t)bh * 64 + d) * 8192 + n;
                            g_vTh[idx] = sh; g_vTl[idx] = sl;
                        }
                    }
                }
    } else {
#pragma unroll
        for (int mt = 0; mt < 2; ++mt)
#pragma unroll
            for (int nt = 0; nt < 8; ++nt)
#pragma unroll
                for (int dd = 0; dd < 2; ++dd) {
                    int row = rbase + mt * 16 + dd * 8;
                    int col = cbase + nt * 8;
                    float2 v;
                    v.x = acc[mt][nt][dd * 2 + 0] + bias[col];
                    v.y = acc[mt][nt][dd * 2 + 1] + bias[col + 1];
                    *(float2*)(C + (size_t)row * ldc + col) = v;
                }
    }
}

// ---------------- tensorized windowed attention ----------------
// grid (qt=4, win=32, bh=24), 256 threads (8 warps).
// smem layout (bytes):
//   sQ   @0      : Qch, Qcl, Qph, Qpl     4 x 64x144  = 36864
//   buf1 @36864  : relK hi/lo (2x46080) -> K hi/lo (2x36864) -> S f32 (64x260x4)
//                  -> V^T hi/lo (2x33792)                      region = 92160
//   buf2 @129024 : G f32 (64 x 324 x 4 = 82944) -> Ph/Pl (2x33792)
#define AT_Q    0
#define AT_B1   36864
#define AT_B2   129024
#define AT_BYTES 211968
__global__ __launch_bounds__(256, 1) void attn_kernel(
    const __nv_bfloat16* __restrict__ RKh, const __nv_bfloat16* __restrict__ RKl,
    const float* __restrict__ rcb, const float* __restrict__ rpb)
{
    extern __shared__ __align__(16) char smem[];
    uint32_t sb = smem_u32(smem);
    int qt = blockIdx.x, win = blockIdx.y, bh = blockIdx.z;
    int bb = bh / 12;
    int hd = bh - bb * 12;              // head
    int tid = threadIdx.x, lane = tid & 31, wid = tid >> 5;

    int aRow  = (lane & 7) + ((lane >> 3) & 1) * 8;
    int aColB = ((lane >> 4) & 1) * 16;
    int bRow  = lane & 7;
    int bColB = ((lane >> 3) & 1) * 16;

    // ---- stage Q (fp32 -> biased, scaled, split) ----
    {
        const float* qbase = g_q + ((size_t)bh * 8192 + win * 256 + qt * 64) * 64;
        __nv_bfloat16* sQch = (__nv_bfloat16*)(smem + AT_Q);
        __nv_bfloat16* sQcl = (__nv_bfloat16*)(smem + AT_Q + 9216);
        __nv_bfloat16* sQph = (__nv_bfloat16*)(smem + AT_Q + 18432);
        __nv_bfloat16* sQpl = (__nv_bfloat16*)(smem + AT_Q + 27648);
#pragma unroll
        for (int it = 0; it < 4; ++it) {
            int e = (it * 256 + tid) * 4;
            int ii = e >> 6, d = e & 63;
            float4 qv = *(const float4*)(qbase + ii * 64 + d);
            float4 cb = *(const float4*)(rcb + hd * 64 + d);
            float4 pb = *(const float4*)(rpb + hd * 64 + d);
            float qc[4] = {(qv.x + cb.x) * 0.125f, (qv.y + cb.y) * 0.125f,
                           (qv.z + cb.z) * 0.125f, (qv.w + cb.w) * 0.125f};
            float qp[4] = {qv.x + pb.x, qv.y + pb.y, qv.z + pb.z, qv.w + pb.w};
#pragma unroll
            for (int c = 0; c < 4; ++c) {
                __nv_bfloat16 hh, ll;
                split2(qc[c], hh, ll);
                sQch[ii * 72 + d + c] = hh; sQcl[ii * 72 + d + c] = ll;
                split2(qp[c], hh, ll);
                sQph[ii * 72 + d + c] = hh; sQpl[ii * 72 + d + c] = ll;
            }
        }
    }
    // ---- stage relK slab [u][d], u=0..319, idx = base_rel + u ----
    int base_rel = 192 - qt * 64;
#pragma unroll
    for (int it = 0; it < 20; ++it) {
        int g = it * 256 + tid;             // 0..5119
        int arr = g >= 2560;
        int gg = arr ? g - 2560 : g;
        int u = gg >> 3, c = gg & 7;
        int idx = base_rel + u;
        uint4 val = make_uint4(0, 0, 0, 0);
        const __nv_bfloat16* src = arr ? RKl : RKh;
        if (idx <= 510)
            val = *(const uint4*)(src + (size_t)idx * 768 + hd * 64 + c * 8);
        *(uint4*)(smem + AT_B1 + arr * 46080 + u * 144 + c * 16) = val;
    }
    __syncthreads();

    // ---- phase G: G[64][320] = Qp x relK^T ----
    {
        uint32_t qpH = sb + AT_Q + 18432, qpL = sb + AT_Q + 27648;
        uint32_t rkH = sb + AT_B1, rkL = sb + AT_B1 + 46080;
        float accG[20][4] = {};
#pragma unroll
        for (int ks = 0; ks < 4; ++ks) {
            uint32_t ah[4][4], al[4][4];
#pragma unroll
            for (int mt = 0; mt < 4; ++mt) {
                uint32_t ra = (uint32_t)(mt * 16 + aRow) * 144 + ks * 32 + aColB;
                ldsm4(ah[mt], qpH + ra);
                ldsm4(al[mt], qpL + ra);
            }
#pragma unroll
            for (int ntl = 0; ntl < 5; ++ntl) {
                uint32_t rb = (uint32_t)(wid * 40 + ntl * 8 + bRow) * 144 + ks * 32 + bColB;
                uint32_t bhf[2], blf[2];
                ldsm2(bhf, rkH + rb);
                ldsm2(blf, rkL + rb);
#pragma unroll
                for (int mt = 0; mt < 4; ++mt) {
                    mma_bf16(accG[mt * 5 + ntl], ah[mt], bhf);
                    mma_bf16(accG[mt * 5 + ntl], ah[mt], blf);
                    mma_bf16(accG[mt * 5 + ntl], al[mt], bhf);
                }
            }
        }
        __syncthreads();   // relK reads done
        // write G to buf2, load K into buf1
        float* sG = (float*)(smem + AT_B2);
#pragma unroll
        for (int mt = 0; mt < 4; ++mt)
#pragma unroll
            for (int ntl = 0; ntl < 5; ++ntl) {
                int r0 = mt * 16 + (lane >> 2);
                int c0 = wid * 40 + ntl * 8 + (lane & 3) * 2;
                float* a4 = accG[mt * 5 + ntl];
                sG[r0 * 324 + c0]       = a4[0];
                sG[r0 * 324 + c0 + 1]   = a4[1];
                sG[(r0 + 8) * 324 + c0]     = a4[2];
                sG[(r0 + 8) * 324 + c0 + 1] = a4[3];
            }
#pragma unroll
        for (int it = 0; it < 16; ++it) {
            int g = it * 256 + tid;          // 0..4095
            int arr = g >= 2048;
            int gg = g & 2047;
            int j = gg >> 3, c = gg & 7;
            const __nv_bfloat16* src = arr ? g_kl : g_kh;
            uint4 val = *(const uint4*)(src + ((size_t)bh * 8192 + win * 256 + j) * 64 + c * 8);
            *(uint4*)(smem + AT_B1 + arr * 36864 + j * 144 + c * 16) = val;
        }
    }
    __syncthreads();

    // ---- phase S: S[64][256] = Qc x K^T, += gather(G) ----
    {
        uint32_t qcH = sb + AT_Q, qcL = sb + AT_Q + 9216;
        uint32_t kH = sb + AT_B1, kL = sb + AT_B1 + 36864;
        float accS[16][4] = {};
#pragma unroll
        for (int ks = 0; ks < 4; ++ks) {
            uint32_t ah[4][4], al[4][4];
#pragma unroll
            for (int mt = 0; mt < 4; ++mt) {
                uint32_t ra = (uint32_t)(mt * 16 + aRow) * 144 + ks * 32 + aColB;
                ldsm4(ah[mt], qcH + ra);
                ldsm4(al[mt], qcL + ra);
            }
#pragma unroll
            for (int ntl = 0; ntl < 4; ++ntl) {
                uint32_t rb = (uint32_t)(wid * 32 + ntl * 8 + bRow) * 144 + ks * 32 + bColB;
                uint32_t bhf[2], blf[2];
                ldsm2(bhf, kH + rb);
                ldsm2(blf, kL + rb);
#pragma unroll
                for (int mt = 0; mt < 4; ++mt) {
                    mma_bf16(accS[mt * 4 + ntl], ah[mt], bhf);
                    mma_bf16(accS[mt * 4 + ntl], ah[mt], blf);
                    mma_bf16(accS[mt * 4 + ntl], al[mt], bhf);
                }
            }
        }
        __syncthreads();   // K reads done -> buf1 reusable for S
        float* sS = (float*)(smem + AT_B1);
        float* sG = (float*)(smem + AT_B2);
#pragma unroll
        for (int mt = 0; mt < 4; ++mt)
#pragma unroll
            for (int ntl = 0; ntl < 4; ++ntl) {
                int r0 = mt * 16 + (lane >> 2);
                int c0 = wid * 32 + ntl * 8 + (lane & 3) * 2;
                float* a4 = accS[mt * 4 + ntl];
                sS[r0 * 260 + c0]     = a4[0] + sG[r0 * 324 + (c0 - r0 + 63)];
                sS[r0 * 260 + c0 + 1] = a4[1] + sG[r0 * 324 + (c0 + 1 - r0 + 63)];
                sS[(r0 + 8) * 260 + c0]     = a4[2] + sG[(r0 + 8) * 324 + (c0 - r0 - 8 + 63)];
                sS[(r0 + 8) * 260 + c0 + 1] = a4[3] + sG[(r0 + 8) * 324 + (c0 + 1 - r0 - 8 + 63)];
            }
    }
    __syncthreads();

    // ---- softmax (SIMT, warp = 8 rows) + P split into buf2 ----
    {
        float* sS = (float*)(smem + AT_B1);
        __nv_bfloat16* sPh = (__nv_bfloat16*)(smem + AT_B2);
        __nv_bfloat16* sPl = (__nv_bfloat16*)(smem + AT_B2 + 33792);
#pragma unroll
        for (int r = 0; r < 8; ++r) {
            int row = wid * 8 + r;
            float v[8];
            *(float4*)(v)     = *(float4*)(sS + row * 260 + lane * 4);
            *(float4*)(v + 4) = *(float4*)(sS + row * 260 + 128 + lane * 4);
            float m = v[0];
#pragma unroll
            for (int c = 1; c < 8; ++c) m = fmaxf(m, v[c]);
#pragma unroll
            for (int off = 16; off > 0; off >>= 1)
                m = fmaxf(m, __shfl_xor_sync(0xffffffffu, m, off));
            float s = 0.f;
#pragma unroll
            for (int c = 0; c < 8; ++c) { v[c] = expf(v[c] - m); s += v[c]; }
#pragma unroll
            for (int off = 16; off > 0; off >>= 1)
                s += __shfl_xor_sync(0xffffffffu, s, off);
            float inv = 1.0f / s;
            __nv_bfloat16 hh[8], ll[8];
#pragma unroll
            for (int c = 0; c < 8; ++c) split2(v[c] * inv, hh[c], ll[c]);
            __nv_bfloat162 p0 = {hh[0], hh[1]}, p1 = {hh[2], hh[3]};
            __nv_bfloat162 p2 = {hh[4], hh[5]}, p3 = {hh[6], hh[7]};
            __nv_bfloat162 q0 = {ll[0], ll[1]}, q1 = {ll[2], ll[3]};
            __nv_bfloat162 q2 = {ll[4], ll[5]}, q3 = {ll[6], ll[7]};
            *(__nv_bfloat162*)(sPh + row * 264 + lane * 4)           = p0;
            *(__nv_bfloat162*)(sPh + row * 264 + lane * 4 + 2)       = p1;
            *(__nv_bfloat162*)(sPh + row * 264 + 128 + lane * 4)     = p2;
            *(__nv_bfloat162*)(sPh + row * 264 + 128 + lane * 4 + 2) = p3;
            *(__nv_bfloat162*)(sPl + row * 264 + lane * 4)           = q0;
            *(__nv_bfloat162*)(sPl + row * 264 + lane * 4 + 2)       = q1;
            *(__nv_bfloat162*)(sPl + row * 264 + 128 + lane * 4)     = q2;
            *(__nv_bfloat162*)(sPl + row * 264 + 128 + lane * 4 + 2) = q3;
        }
    }
    __syncthreads();

    // ---- load V^T [d][j] into buf1 ----
#pragma unroll
    for (int it = 0; it < 16; ++it) {
        int g = it * 256 + tid;              // 0..4095
        int arr = g >= 2048;
        int gg = g & 2047;
        int d = gg >> 5, c = gg & 31;
        const __nv_bfloat16* src = arr ? g_vTl : g_vTh;
        uint4 val = *(const uint4*)(src + ((size_t)bh * 64 + d) * 8192 + win * 256 + c * 8);
        *(uint4*)(smem + AT_B1 + arr * 33792 + d * 528 + c * 16) = val;
    }
    __syncthreads();

    // ---- phase AV: O[64][64] = P x V ----
    {
        uint32_t pH = sb + AT_B2, pL = sb + AT_B2 + 33792;
        uint32_t vH = sb + AT_B1, vL = sb + AT_B1 + 33792;
        int mtA = wid >> 1;
        int d0 = (wid & 1) * 32;
        float accO[4][4] = {};
#pragma unroll
        for (int ks = 0; ks < 16; ++ks) {
            uint32_t ah[4], al[4];
            uint32_t ra = (uint32_t)(mtA * 16 + aRow) * 528 + ks * 32 + aColB;
            ldsm4(ah, pH + ra);
            ldsm4(al, pL + ra);
#pragma unroll
            for (int ntl = 0; ntl < 4; ++ntl) {
                uint32_t rb = (uint32_t)(d0 + ntl * 8 + bRow) * 528 + ks * 32 + bColB;
                uint32_t bhf[2], blf[2];
                ldsm2(bhf, vH + rb);
                ldsm2(blf, vL + rb);
                mma_bf16(accO[ntl], ah, bhf);
                mma_bf16(accO[ntl], ah, blf);
                mma_bf16(accO[ntl], al, bhf);
            }
        }
        float* out0 = g_attn + ((size_t)bb * 8192 + win * 256 + qt * 64) * 768 + hd * 64;
#pragma unroll
        for (int ntl = 0; ntl < 4; ++ntl) {
            int row = mtA * 16 + (lane >> 2);
            int col = d0 + ntl * 8 + (lane & 3) * 2;
            float2 v0 = {accO[ntl][0], accO[ntl][1]};
            float2 v1 = {accO[ntl][2], accO[ntl][3]};
            *(float2*)(out0 + (size_t)row * 768 + col) = v0;
            *(float2*)(out0 + (size_t)(row + 8) * 768 + col) = v1;
        }
    }
}

// ---------------- launch ----------------
extern "C" void kernel_launch(void* const* d_in, const int* in_sizes, int n_in,
                              void* d_out, int out_size)
{
    const float* x    = (const float*)d_in[0];
    const float* wqkv = (const float*)d_in[1];
    const float* wout = (const float*)d_in[2];
    const float* bout = (const float*)d_in[3];
    const float* wrel = (const float*)d_in[4];
    const float* rcb  = (const float*)d_in[5];
    const float* rpb  = (const float*)d_in[6];
    float* out = (float*)d_out;

    float *P, *RK, *attn;
    __nv_bfloat16 *xh, *xl, *wqh, *wql, *woh, *wol, *ah, *al, *rkh, *rkl;
    cudaGetSymbolAddress((void**)&P,    g_P);
    cudaGetSymbolAddress((void**)&RK,   g_RK);
    cudaGetSymbolAddress((void**)&attn, g_attn);
    cudaGetSymbolAddress((void**)&xh,  g_xh);
    cudaGetSymbolAddress((void**)&xl,  g_xl);
    cudaGetSymbolAddress((void**)&wqh, g_wqh);
    cudaGetSymbolAddress((void**)&wql, g_wql);
    cudaGetSymbolAddress((void**)&woh, g_woh);
    cudaGetSymbolAddress((void**)&wol, g_wol);
    cudaGetSymbolAddress((void**)&ah,  g_ah);
    cudaGetSymbolAddress((void**)&al,  g_al);
    cudaGetSymbolAddress((void**)&rkh, g_RKh);
    cudaGetSymbolAddress((void**)&rkl, g_RKl);

    cudaFuncSetAttribute(attn_kernel,
                         cudaFuncAttributeMaxDynamicSharedMemorySize, AT_BYTES);
    cudaFuncSetAttribute(mma_gemm<0>,
                         cudaFuncAttributeMaxDynamicSharedMemorySize, MM_BYTES);
    cudaFuncSetAttribute(mma_gemm<1>,
                         cudaFuncAttributeMaxDynamicSharedMemorySize, MM_BYTES);

    // 1) positional embedding + rel_k (SIMT; small), then split rel_k
    pos_kernel<<<511, 128>>>(P);
    gemm_bias_kernel<<<dim3(6, 4), 256>>>(P, wrel, RK, nullptr, 511, 768, 768);
    conv_split<<<(511 * 768 / 4 + 255) / 256, 256>>>(RK, rkh, rkl, 511 * 768);

    // 2) split x and transpose-split w_qkv
    conv_split<<<16384 * 768 / 1024, 256>>>(x, xh, xl, 16384 * 768);
    conv_split_T<<<dim3(2304 / 32, 768 / 32), dim3(32, 8)>>>(wqkv, wqh, wql, 768, 2304);

    // 3) QKV projection (tensor cores; writes q fp32, k/v split bf16, v transposed)
    mma_gemm<0><<<dim3(18, 128), 256, MM_BYTES>>>(xh, xl, wqh, wql, 768,
                                                  nullptr, nullptr, 0);

    // 4) tensorized windowed attention
    attn_kernel<<<dim3(4, 32, 24), 256, AT_BYTES>>>(rkh, rkl, rcb, rpb);

    // 5) split attn output + transpose-split w_out; output projection (tensor cores)
    conv_split<<<16384 * 768 / 1024, 256>>>(attn, ah, al, 16384 * 768);
    conv_split_T<<<dim3(768 / 32, 768 / 32), dim3(32, 8)>>>(wout, woh, wol, 768, 768);
    mma_gemm<1><<<dim3(6, 128), 256, MM_BYTES>>>(ah, al, woh, wol, 768,
                                                 bout, out, 768);
}

// round 17
// speedup vs baseline: 2.0066x; 1.0478x over previous
#include <cuda_runtime.h>
#include <cuda_bf16.h>
#include <stdint.h>
#include <math.h>

// ---------------- scratch (device globals; no allocation allowed) ----------------
__device__ __align__(16) float g_q[2 * 12 * 8192 * 64];
__device__ __align__(16) float g_P[511 * 768];
// split-bf16 operands
__device__ __align__(16) __nv_bfloat16 g_xh[16384 * 768];
__device__ __align__(16) __nv_bfloat16 g_xl[16384 * 768];
__device__ __align__(16) __nv_bfloat16 g_wqh[2304 * 768];   // transposed [N][K]
__device__ __align__(16) __nv_bfloat16 g_wql[2304 * 768];
__device__ __align__(16) __nv_bfloat16 g_woh[768 * 768];    // transposed [N][K]
__device__ __align__(16) __nv_bfloat16 g_wol[768 * 768];
__device__ __align__(16) __nv_bfloat16 g_ah[16384 * 768];
__device__ __align__(16) __nv_bfloat16 g_al[16384 * 768];
// attention operands (split, produced by QKV epilogue)
__device__ __align__(16) __nv_bfloat16 g_kh[2 * 12 * 8192 * 64];   // [bh][n][d]
__device__ __align__(16) __nv_bfloat16 g_kl[2 * 12 * 8192 * 64];
__device__ __align__(16) __nv_bfloat16 g_vTh[2 * 12 * 64 * 8192];  // [bh][d][n]
__device__ __align__(16) __nv_bfloat16 g_vTl[2 * 12 * 64 * 8192];
__device__ __align__(16) __nv_bfloat16 g_RKh[511 * 768];
__device__ __align__(16) __nv_bfloat16 g_RKl[511 * 768];

// ---------------- warp-MMA helpers (base-PTX; validated in R15/R16) --------------
__device__ __forceinline__ uint32_t smem_u32(const void* p) {
    uint32_t a;
    asm("{ .reg .u64 t; cvta.to.shared.u64 t, %1; cvt.u32.u64 %0, t; }" : "=r"(a) : "l"(p));
    return a;
}
__device__ __forceinline__ void ldsm4(uint32_t* r, uint32_t a) {
    asm volatile("ldmatrix.sync.aligned.m8n8.x4.shared.b16 {%0,%1,%2,%3}, [%4];"
        : "=r"(r[0]), "=r"(r[1]), "=r"(r[2]), "=r"(r[3]) : "r"(a));
}
__device__ __forceinline__ void ldsm2(uint32_t* r, uint32_t a) {
    asm volatile("ldmatrix.sync.aligned.m8n8.x2.shared.b16 {%0,%1}, [%2];"
        : "=r"(r[0]), "=r"(r[1]) : "r"(a));
}
__device__ __forceinline__ void mma_bf16(float* d, const uint32_t* a, const uint32_t* b) {
    asm volatile("mma.sync.aligned.m16n8k16.row.col.f32.bf16.bf16.f32 "
        "{%0,%1,%2,%3}, {%4,%5,%6,%7}, {%8,%9}, {%0,%1,%2,%3};"
        : "+f"(d[0]), "+f"(d[1]), "+f"(d[2]), "+f"(d[3])
        : "r"(a[0]), "r"(a[1]), "r"(a[2]), "r"(a[3]), "r"(b[0]), "r"(b[1]));
}
__device__ __forceinline__ void split2(float v, __nv_bfloat16& hh, __nv_bfloat16& ll) {
    hh = __float2bfloat16(v);
    ll = __float2bfloat16(v - __bfloat162float(hh));
}
__device__ __forceinline__ void cp16(uint32_t dst, const void* src) {
    asm volatile("cp.async.cg.shared.global [%0], [%1], 16;" :: "r"(dst), "l"(src));
}
#define CP_COMMIT() asm volatile("cp.async.commit_group;" ::: "memory")
#define CP_WAIT(n)  asm volatile("cp.async.wait_group %0;" :: "n"(n) : "memory")

// ---------------- positional embedding (511 x 768) ----------------
__global__ void pos_kernel(float* __restrict__ P) {
    int row = blockIdx.x;
    int f = threadIdx.x;
    float dist = (float)(row - 255);
    float absd = fabsf(dist);

    float hl = exp2f(3.0f + (float)f * (5.0f / 127.0f));
    float fe = expf(-(0.6931471805599453f / hl) * absd);
    float cw = exp2f((float)(f + 1)) - 1.0f;
    float fc = (cw > absd) ? 1.0f : 0.0f;
    double mean = 2.0 + 2.0 * (double)f;
    double conc = mean * mean;
    double lu;
    if (absd > 0.0f) lu = (conc - 1.0) * log((double)absd) - mean * (double)absd;
    else             lu = -INFINITY;
    double lnorm = lgamma(conc) - conc * log(mean);
    double prob = exp(lu - lnorm) + 1e-8;

    __shared__ double red[128];
    red[f] = prob;
    __syncthreads();
    for (int s = 64; s > 0; s >>= 1) {
        if (f < s) red[f] = fmax(red[f], red[f + s]);
        __syncthreads();
    }
    double mp = red[0];
    float fg = (float)(prob / mp);

    float sgn = (dist > 0.f) ? 1.f : ((dist < 0.f) ? -1.f : 0.f);
    float* Pr = P + (size_t)row * 768;
    Pr[f]       = fe;  Pr[128 + f] = fc;        Pr[256 + f] = fg;
    Pr[384 + f] = sgn * fe; Pr[512 + f] = sgn * fc; Pr[640 + f] = sgn * fg;
}

// ---------------- fp32 SIMT GEMM with split-bf16 epilogue (relk: 511x768x768) ----
__global__ __launch_bounds__(256, 2) void gemm_split_kernel(
    const float* __restrict__ A, const float* __restrict__ B,
    __nv_bfloat16* __restrict__ Oh, __nv_bfloat16* __restrict__ Ol,
    int M, int N, int K)
{
    __shared__ float As[2][16 * 132];
    __shared__ float Bs[2][16 * 128];
    int tid = threadIdx.x;
    int ty = tid >> 4, tx = tid & 15;
    int row0 = blockIdx.y * 128, col0 = blockIdx.x * 128;
    float acc[8][8] = {};

    int mA = tid >> 2, kA = (tid & 3) * 4;
    int kB = tid >> 5, nB = (tid & 31) * 4;

    const float* Ap0 = A + (size_t)(row0 + mA) * K + kA;
    const float* Ap1 = Ap0 + (size_t)64 * K;
    const float* Bp0 = B + (size_t)kB * N + col0 + nB;
    const float* Bp1 = Bp0 + (size_t)8 * N;
    bool ga0 = (row0 + mA) < M;
    bool ga1 = (row0 + mA + 64) < M;
    const float4 z4 = make_float4(0.f, 0.f, 0.f, 0.f);

    float4 ra0 = ga0 ? *(const float4*)(Ap0) : z4;
    float4 ra1 = ga1 ? *(const float4*)(Ap1) : z4;
    float4 rb0 = *(const float4*)(Bp0);
    float4 rb1 = *(const float4*)(Bp1);
    int p = 0;
    {
        float* as = As[0]; float* bs = Bs[0];
        as[(kA + 0) * 132 + mA] = ra0.x; as[(kA + 1) * 132 + mA] = ra0.y;
        as[(kA + 2) * 132 + mA] = ra0.z; as[(kA + 3) * 132 + mA] = ra0.w;
        as[(kA + 0) * 132 + mA + 64] = ra1.x; as[(kA + 1) * 132 + mA + 64] = ra1.y;
        as[(kA + 2) * 132 + mA + 64] = ra1.z; as[(kA + 3) * 132 + mA + 64] = ra1.w;
        *(float4*)(bs + kB * 128 + nB) = rb0;
        *(float4*)(bs + (kB + 8) * 128 + nB) = rb1;
    }
    __syncthreads();

    for (int kt = 16; kt < K; kt += 16) {
        ra0 = ga0 ? *(const float4*)(Ap0 + kt) : z4;
        ra1 = ga1 ? *(const float4*)(Ap1 + kt) : z4;
        rb0 = *(const float4*)(Bp0 + (size_t)kt * N);
        rb1 = *(const float4*)(Bp1 + (size_t)kt * N);
        {
            const float* as = As[p]; const float* bs = Bs[p];
#pragma unroll
            for (int kk = 0; kk < 16; ++kk) {
                float a[8], b[8];
                *(float4*)(a)     = *(const float4*)(as + kk * 132 + ty * 8);
                *(float4*)(a + 4) = *(const float4*)(as + kk * 132 + ty * 8 + 4);
                *(float4*)(b)     = *(const float4*)(bs + kk * 128 + tx * 8);
                *(float4*)(b + 4) = *(const float4*)(bs + kk * 128 + tx * 8 + 4);
#pragma unroll
                for (int r = 0; r < 8; ++r)
#pragma unroll
                    for (int c = 0; c < 8; ++c)
                        acc[r][c] = fmaf(a[r], b[c], acc[r][c]);
            }
        }
        {
            float* as = As[p ^ 1]; float* bs = Bs[p ^ 1];
            as[(kA + 0) * 132 + mA] = ra0.x; as[(kA + 1) * 132 + mA] = ra0.y;
            as[(kA + 2) * 132 + mA] = ra0.z; as[(kA + 3) * 132 + mA] = ra0.w;
            as[(kA + 0) * 132 + mA + 64] = ra1.x; as[(kA + 1) * 132 + mA + 64] = ra1.y;
            as[(kA + 2) * 132 + mA + 64] = ra1.z; as[(kA + 3) * 132 + mA + 64] = ra1.w;
            *(float4*)(bs + kB * 128 + nB) = rb0;
            *(float4*)(bs + (kB + 8) * 128 + nB) = rb1;
        }
        __syncthreads();
        p ^= 1;
    }
    {
        const float* as = As[p]; const float* bs = Bs[p];
#pragma unroll
        for (int kk = 0; kk < 16; ++kk) {
            float a[8], b[8];
            *(float4*)(a)     = *(const float4*)(as + kk * 132 + ty * 8);
            *(float4*)(a + 4) = *(const float4*)(as + kk * 132 + ty * 8 + 4);
            *(float4*)(b)     = *(const float4*)(bs + kk * 128 + tx * 8);
            *(float4*)(b + 4) = *(const float4*)(bs + kk * 128 + tx * 8 + 4);
#pragma unroll
            for (int r = 0; r < 8; ++r)
#pragma unroll
                for (int c = 0; c < 8; ++c)
                    acc[r][c] = fmaf(a[r], b[c], acc[r][c]);
        }
    }

#pragma unroll
    for (int r = 0; r < 8; ++r) {
        int row = row0 + ty * 8 + r;
        if (row < M) {
#pragma unroll
            for (int c = 0; c < 8; ++c) {
                __nv_bfloat16 hh, ll;
                split2(acc[r][c], hh, ll);
                Oh[(size_t)row * N + col0 + tx * 8 + c] = hh;
                Ol[(size_t)row * N + col0 + tx * 8 + c] = ll;
            }
        }
    }
}

// ---------------- fp32 -> (hi, lo) bf16 split, elementwise ----------------
__global__ __launch_bounds__(256) void conv_split(
    const float* __restrict__ in, __nv_bfloat16* __restrict__ oh,
    __nv_bfloat16* __restrict__ ol, int n)
{
    int i = (blockIdx.x * 256 + threadIdx.x) * 4;
    if (i >= n) return;
    float4 v = *(const float4*)(in + i);
    __nv_bfloat16 h0, h1, h2, h3, l0, l1, l2, l3;
    split2(v.x, h0, l0); split2(v.y, h1, l1);
    split2(v.z, h2, l2); split2(v.w, h3, l3);
    __nv_bfloat162 hp0 = {h0, h1}, hp1 = {h2, h3}, lp0 = {l0, l1}, lp1 = {l2, l3};
    *(__nv_bfloat162*)(oh + i)     = hp0;
    *(__nv_bfloat162*)(oh + i + 2) = hp1;
    *(__nv_bfloat162*)(ol + i)     = lp0;
    *(__nv_bfloat162*)(ol + i + 2) = lp1;
}

// ---------------- fp32 [K][N] -> transposed (hi, lo) bf16 [N][K] ----------------
__global__ __launch_bounds__(256) void conv_split_T(
    const float* __restrict__ in, __nv_bfloat16* __restrict__ oh,
    __nv_bfloat16* __restrict__ ol, int K, int N)
{
    __shared__ float t[32][33];
    int n0 = blockIdx.x * 32, k0 = blockIdx.y * 32;
    int tx = threadIdx.x, ty = threadIdx.y;    // block (32, 8)
#pragma unroll
    for (int r = 0; r < 4; ++r)
        t[ty + r * 8][tx] = in[(size_t)(k0 + ty + r * 8) * N + n0 + tx];
    __syncthreads();
#pragma unroll
    for (int r = 0; r < 4; ++r) {
        int nn = ty + r * 8;
        float v = t[tx][nn];
        __nv_bfloat16 hh, ll;
        split2(v, hh, ll);
        size_t idx = (size_t)(n0 + nn) * K + k0 + tx;
        oh[idx] = hh;
        ol[idx] = ll;
    }
}

// ---------------- mma.sync split-bf16 GEMM, cp.async double-buffered ------------
// A: [M][K] bf16 hi/lo. B: [N][K] bf16 hi/lo. Tile 128x128, K-chunks of 64, 2 stages.
// MODE 0: scatter q fp32 / k split / vT split.  MODE 1: +bias -> C row-major fp32.
#define MM_STRIDE 144
#define SM_AH 0
#define SM_AL 18432
#define SM_BH 36864
#define SM_BL 55296
#define MM_STAGE 73728
#define MM_BYTES (2 * MM_STAGE)
template <int MODE>
__global__ __launch_bounds__(256, 1) void mma_gemm(
    const __nv_bfloat16* __restrict__ Ah, const __nv_bfloat16* __restrict__ Al,
    const __nv_bfloat16* __restrict__ Bh, const __nv_bfloat16* __restrict__ Bl,
    int K, const float* __restrict__ bias, float* __restrict__ C, int ldc)
{
    extern __shared__ __align__(16) char smem[];
    uint32_t sb = smem_u32(smem);
    int tid = threadIdx.x, lane = tid & 31, wid = tid >> 5;
    int wm = wid & 3, wn = wid >> 2;
    int m0 = blockIdx.y * 128, n0 = blockIdx.x * 128;
    float acc[2][8][4] = {};

    int aRow  = (lane & 7) + ((lane >> 3) & 1) * 8;
    int aColB = ((lane >> 4) & 1) * 16;
    int bRow4 = (lane & 7) + ((lane >> 4) & 1) * 8;   // B x4: groups 2,3 -> next nt tile
    int bCol4 = ((lane >> 3) & 1) * 16;

    // per-thread staging coordinates (4 granules per array per chunk)
    int sRow[4], sCol[4];
#pragma unroll
    for (int i = 0; i < 4; ++i) {
        int g = tid + i * 256;
        sRow[i] = g >> 3; sCol[i] = g & 7;
    }

    int nchunks = K >> 6;
    // prefetch chunk 0 -> stage 0
#pragma unroll
    for (int i = 0; i < 4; ++i) {
        uint32_t doff = (uint32_t)sRow[i] * MM_STRIDE + sCol[i] * 16;
        size_t asrc = (size_t)(m0 + sRow[i]) * K + sCol[i] * 8;
        size_t bsrc = (size_t)(n0 + sRow[i]) * K + sCol[i] * 8;
        cp16(sb + SM_AH + doff, Ah + asrc);
        cp16(sb + SM_AL + doff, Al + asrc);
        cp16(sb + SM_BH + doff, Bh + bsrc);
        cp16(sb + SM_BL + doff, Bl + bsrc);
    }
    CP_COMMIT();

    for (int kc = 0; kc < nchunks; ++kc) {
        uint32_t st = (uint32_t)(kc & 1) * MM_STAGE;
        if (kc + 1 < nchunks) {
            uint32_t st2 = (uint32_t)((kc + 1) & 1) * MM_STAGE;
            int ko = (kc + 1) << 6;
#pragma unroll
            for (int i = 0; i < 4; ++i) {
                uint32_t doff = st2 + (uint32_t)sRow[i] * MM_STRIDE + sCol[i] * 16;
                size_t asrc = (size_t)(m0 + sRow[i]) * K + ko + sCol[i] * 8;
                size_t bsrc = (size_t)(n0 + sRow[i]) * K + ko + sCol[i] * 8;
                cp16(sb + SM_AH + doff, Ah + asrc);
                cp16(sb + SM_AL + doff, Al + asrc);
                cp16(sb + SM_BH + doff, Bh + bsrc);
                cp16(sb + SM_BL + doff, Bl + bsrc);
            }
            CP_COMMIT();
            CP_WAIT(1);
        } else {
            CP_WAIT(0);
        }
        __syncthreads();
#pragma unroll
        for (int ks = 0; ks < 4; ++ks) {
            uint32_t ah[2][4], al[2][4];
#pragma unroll
            for (int mt = 0; mt < 2; ++mt) {
                uint32_t ra = st + (uint32_t)(wm * 32 + mt * 16 + aRow) * MM_STRIDE + ks * 32 + aColB;
                ldsm4(ah[mt], sb + SM_AH + ra);
                ldsm4(al[mt], sb + SM_AL + ra);
            }
#pragma unroll
            for (int ntp = 0; ntp < 4; ++ntp) {
                uint32_t rb = st + (uint32_t)(wn * 64 + ntp * 16 + bRow4) * MM_STRIDE + ks * 32 + bCol4;
                uint32_t bh4[4], bl4[4];
                ldsm4(bh4, sb + SM_BH + rb);
                ldsm4(bl4, sb + SM_BL + rb);
#pragma unroll
                for (int half = 0; half < 2; ++half) {
                    uint32_t* bhf = bh4 + half * 2;
                    uint32_t* blf = bl4 + half * 2;
                    int nt = ntp * 2 + half;
#pragma unroll
                    for (int mt = 0; mt < 2; ++mt) {
                        mma_bf16(acc[mt][nt], ah[mt], bhf);
                        mma_bf16(acc[mt][nt], ah[mt], blf);
                        mma_bf16(acc[mt][nt], al[mt], bhf);
                    }
                }
            }
        }
        __syncthreads();   // compute done before stage st is overwritten at kc+2
    }

    int rbase = m0 + wm * 32 + (lane >> 2);
    int cbase = n0 + wn * 64 + (lane & 3) * 2;
    if (MODE == 0) {
        // scatter: col = h*192 + d*3 + sel. q -> fp32; k -> bf16 hi/lo; v -> transposed bf16 hi/lo
#pragma unroll
        for (int mt = 0; mt < 2; ++mt)
#pragma unroll
            for (int nt = 0; nt < 8; ++nt)
#pragma unroll
                for (int dd = 0; dd < 2; ++dd) {
                    int row = rbase + mt * 16 + dd * 8;
                    int bidx = row >> 13, n = row & 8191;
#pragma unroll
                    for (int jj = 0; jj < 2; ++jj) {
                        int col = cbase + nt * 8 + jj;
                        int hh = col / 192;
                        int rem = col - hh * 192;
                        int d = rem / 3;
                        int sel = rem - d * 3;
                        int bh = bidx * 12 + hh;
                        float v = acc[mt][nt][dd * 2 + jj];
                        if (sel == 0) {
                            g_q[((size_t)bh * 8192 + n) * 64 + d] = v;
                        } else if (sel == 1) {
                            __nv_bfloat16 sh, sl;
                            split2(v, sh, sl);
                            size_t idx = ((size_t)bh * 8192 + n) * 64 + d;
                            g_kh[idx] = sh; g_kl[idx] = sl;
                        } else {
                            __nv_bfloat16 sh, sl;
                            split2(v, sh, sl);
                            size_t idx = ((size_t)bh * 64 + d) * 8192 + n;
                            g_vTh[idx] = sh; g_vTl[idx] = sl;
                        }
                    }
                }
    } else {
#pragma unroll
        for (int mt = 0; mt < 2; ++mt)
#pragma unroll
            for (int nt = 0; nt < 8; ++nt)
#pragma unroll
                for (int dd = 0; dd < 2; ++dd) {
                    int row = rbase + mt * 16 + dd * 8;
                    int col = cbase + nt * 8;
                    float2 v;
                    v.x = acc[mt][nt][dd * 2 + 0] + bias[col];
                    v.y = acc[mt][nt][dd * 2 + 1] + bias[col + 1];
                    *(float2*)(C + (size_t)row * ldc + col) = v;
                }
    }
}

// ---------------- tensorized windowed attention (fused split epilogue) ----------
// grid (qt=4, win=32, bh=24), 256 threads (8 warps).
#define AT_Q    0
#define AT_B1   36864
#define AT_B2   129024
#define AT_BYTES 211968
__global__ __launch_bounds__(256, 1) void attn_kernel(
    const __nv_bfloat16* __restrict__ RKh, const __nv_bfloat16* __restrict__ RKl,
    const float* __restrict__ rcb, const float* __restrict__ rpb)
{
    extern __shared__ __align__(16) char smem[];
    uint32_t sb = smem_u32(smem);
    int qt = blockIdx.x, win = blockIdx.y, bh = blockIdx.z;
    int bb = bh / 12;
    int hd = bh - bb * 12;
    int tid = threadIdx.x, lane = tid & 31, wid = tid >> 5;

    int aRow  = (lane & 7) + ((lane >> 3) & 1) * 8;
    int aColB = ((lane >> 4) & 1) * 16;
    int bRow  = lane & 7;
    int bColB = ((lane >> 3) & 1) * 16;

    // ---- stage Q (fp32 -> biased, scaled, split) ----
    {
        const float* qbase = g_q + ((size_t)bh * 8192 + win * 256 + qt * 64) * 64;
        __nv_bfloat16* sQch = (__nv_bfloat16*)(smem + AT_Q);
        __nv_bfloat16* sQcl = (__nv_bfloat16*)(smem + AT_Q + 9216);
        __nv_bfloat16* sQph = (__nv_bfloat16*)(smem + AT_Q + 18432);
        __nv_bfloat16* sQpl = (__nv_bfloat16*)(smem + AT_Q + 27648);
#pragma unroll
        for (int it = 0; it < 4; ++it) {
            int e = (it * 256 + tid) * 4;
            int ii = e >> 6, d = e & 63;
            float4 qv = *(const float4*)(qbase + ii * 64 + d);
            float4 cb = *(const float4*)(rcb + hd * 64 + d);
            float4 pb = *(const float4*)(rpb + hd * 64 + d);
            float qc[4] = {(qv.x + cb.x) * 0.125f, (qv.y + cb.y) * 0.125f,
                           (qv.z + cb.z) * 0.125f, (qv.w + cb.w) * 0.125f};
            float qp[4] = {qv.x + pb.x, qv.y + pb.y, qv.z + pb.z, qv.w + pb.w};
#pragma unroll
            for (int c = 0; c < 4; ++c) {
                __nv_bfloat16 hh, ll;
                split2(qc[c], hh, ll);
                sQch[ii * 72 + d + c] = hh; sQcl[ii * 72 + d + c] = ll;
                split2(qp[c], hh, ll);
                sQph[ii * 72 + d + c] = hh; sQpl[ii * 72 + d + c] = ll;
            }
        }
    }
    // ---- stage relK slab [u][d], u=0..319, idx = base_rel + u ----
    int base_rel = 192 - qt * 64;
#pragma unroll
    for (int it = 0; it < 20; ++it) {
        int g = it * 256 + tid;
        int arr = g >= 2560;
        int gg = arr ? g - 2560 : g;
        int u = gg >> 3, c = gg & 7;
        int idx = base_rel + u;
        uint4 val = make_uint4(0, 0, 0, 0);
        const __nv_bfloat16* src = arr ? RKl : RKh;
        if (idx <= 510)
            val = *(const uint4*)(src + (size_t)idx * 768 + hd * 64 + c * 8);
        *(uint4*)(smem + AT_B1 + arr * 46080 + u * 144 + c * 16) = val;
    }
    __syncthreads();

    // ---- phase G: G[64][320] = Qp x relK^T ----
    {
        uint32_t qpH = sb + AT_Q + 18432, qpL = sb + AT_Q + 27648;
        uint32_t rkH = sb + AT_B1, rkL = sb + AT_B1 + 46080;
        float accG[20][4] = {};
#pragma unroll
        for (int ks = 0; ks < 4; ++ks) {
            uint32_t ah[4][4], al[4][4];
#pragma unroll
            for (int mt = 0; mt < 4; ++mt) {
                uint32_t ra = (uint32_t)(mt * 16 + aRow) * 144 + ks * 32 + aColB;
                ldsm4(ah[mt], qpH + ra);
                ldsm4(al[mt], qpL + ra);
            }
#pragma unroll
            for (int ntl = 0; ntl < 5; ++ntl) {
                uint32_t rb = (uint32_t)(wid * 40 + ntl * 8 + bRow) * 144 + ks * 32 + bColB;
                uint32_t bhf[2], blf[2];
                ldsm2(bhf, rkH + rb);
                ldsm2(blf, rkL + rb);
#pragma unroll
                for (int mt = 0; mt < 4; ++mt) {
                    mma_bf16(accG[mt * 5 + ntl], ah[mt], bhf);
                    mma_bf16(accG[mt * 5 + ntl], ah[mt], blf);
                    mma_bf16(accG[mt * 5 + ntl], al[mt], bhf);
                }
            }
        }
        __syncthreads();   // relK reads done
        float* sG = (float*)(smem + AT_B2);
#pragma unroll
        for (int mt = 0; mt < 4; ++mt)
#pragma unroll
            for (int ntl = 0; ntl < 5; ++ntl) {
                int r0 = mt * 16 + (lane >> 2);
                int c0 = wid * 40 + ntl * 8 + (lane & 3) * 2;
                float* a4 = accG[mt * 5 + ntl];
                sG[r0 * 324 + c0]       = a4[0];
                sG[r0 * 324 + c0 + 1]   = a4[1];
                sG[(r0 + 8) * 324 + c0]     = a4[2];
                sG[(r0 + 8) * 324 + c0 + 1] = a4[3];
            }
#pragma unroll
        for (int it = 0; it < 16; ++it) {
            int g = it * 256 + tid;
            int arr = g >= 2048;
            int gg = g & 2047;
            int j = gg >> 3, c = gg & 7;
            const __nv_bfloat16* src = arr ? g_kl : g_kh;
            uint4 val = *(const uint4*)(src + ((size_t)bh * 8192 + win * 256 + j) * 64 + c * 8);
            *(uint4*)(smem + AT_B1 + arr * 36864 + j * 144 + c * 16) = val;
        }
    }
    __syncthreads();

    // ---- phase S: S[64][256] = Qc x K^T, += gather(G) ----
    {
        uint32_t qcH = sb + AT_Q, qcL = sb + AT_Q + 9216;
        uint32_t kH = sb + AT_B1, kL = sb + AT_B1 + 36864;
        float accS[16][4] = {};
#pragma unroll
        for (int ks = 0; ks < 4; ++ks) {
            uint32_t ah[4][4], al[4][4];
#pragma unroll
            for (int mt = 0; mt < 4; ++mt) {
                uint32_t ra = (uint32_t)(mt * 16 + aRow) * 144 + ks * 32 + aColB;
                ldsm4(ah[mt], qcH + ra);
                ldsm4(al[mt], qcL + ra);
            }
#pragma unroll
            for (int ntl = 0; ntl < 4; ++ntl) {
                uint32_t rb = (uint32_t)(wid * 32 + ntl * 8 + bRow) * 144 + ks * 32 + bColB;
                uint32_t bhf[2], blf[2];
                ldsm2(bhf, kH + rb);
                ldsm2(blf, kL + rb);
#pragma unroll
                for (int mt = 0; mt < 4; ++mt) {
                    mma_bf16(accS[mt * 4 + ntl], ah[mt], bhf);
                    mma_bf16(accS[mt * 4 + ntl], ah[mt], blf);
                    mma_bf16(accS[mt * 4 + ntl], al[mt], bhf);
                }
            }
        }
        __syncthreads();   // K reads done -> buf1 reusable for S
        float* sS = (float*)(smem + AT_B1);
        float* sG = (float*)(smem + AT_B2);
#pragma unroll
        for (int mt = 0; mt < 4; ++mt)
#pragma unroll
            for (int ntl = 0; ntl < 4; ++ntl) {
                int r0 = mt * 16 + (lane >> 2);
                int c0 = wid * 32 + ntl * 8 + (lane & 3) * 2;
                float* a4 = accS[mt * 4 + ntl];
                sS[r0 * 260 + c0]     = a4[0] + sG[r0 * 324 + (c0 - r0 + 63)];
                sS[r0 * 260 + c0 + 1] = a4[1] + sG[r0 * 324 + (c0 + 1 - r0 + 63)];
                sS[(r0 + 8) * 260 + c0]     = a4[2] + sG[(r0 + 8) * 324 + (c0 - r0 - 8 + 63)];
                sS[(r0 + 8) * 260 + c0 + 1] = a4[3] + sG[(r0 + 8) * 324 + (c0 + 1 - r0 - 8 + 63)];
            }
    }
    __syncthreads();

    // ---- softmax (SIMT, warp = 8 rows) + P split into buf2 ----
    {
        float* sS = (float*)(smem + AT_B1);
        __nv_bfloat16* sPh = (__nv_bfloat16*)(smem + AT_B2);
        __nv_bfloat16* sPl = (__nv_bfloat16*)(smem + AT_B2 + 33792);
#pragma unroll
        for (int r = 0; r < 8; ++r) {
            int row = wid * 8 + r;
            float v[8];
            *(float4*)(v)     = *(float4*)(sS + row * 260 + lane * 4);
            *(float4*)(v + 4) = *(float4*)(sS + row * 260 + 128 + lane * 4);
            float m = v[0];
#pragma unroll
            for (int c = 1; c < 8; ++c) m = fmaxf(m, v[c]);
#pragma unroll
            for (int off = 16; off > 0; off >>= 1)
                m = fmaxf(m, __shfl_xor_sync(0xffffffffu, m, off));
            float s = 0.f;
#pragma unroll
            for (int c = 0; c < 8; ++c) { v[c] = expf(v[c] - m); s += v[c]; }
#pragma unroll
            for (int off = 16; off > 0; off >>= 1)
                s += __shfl_xor_sync(0xffffffffu, s, off);
            float inv = 1.0f / s;
            __nv_bfloat16 hh[8], ll[8];
#pragma unroll
            for (int c = 0; c < 8; ++c) split2(v[c] * inv, hh[c], ll[c]);
            __nv_bfloat162 p0 = {hh[0], hh[1]}, p1 = {hh[2], hh[3]};
            __nv_bfloat162 p2 = {hh[4], hh[5]}, p3 = {hh[6], hh[7]};
            __nv_bfloat162 q0 = {ll[0], ll[1]}, q1 = {ll[2], ll[3]};
            __nv_bfloat162 q2 = {ll[4], ll[5]}, q3 = {ll[6], ll[7]};
            *(__nv_bfloat162*)(sPh + row * 264 + lane * 4)           = p0;
            *(__nv_bfloat162*)(sPh + row * 264 + lane * 4 + 2)       = p1;
            *(__nv_bfloat162*)(sPh + row * 264 + 128 + lane * 4)     = p2;
            *(__nv_bfloat162*)(sPh + row * 264 + 128 + lane * 4 + 2) = p3;
            *(__nv_bfloat162*)(sPl + row * 264 + lane * 4)           = q0;
            *(__nv_bfloat162*)(sPl + row * 264 + lane * 4 + 2)       = q1;
            *(__nv_bfloat162*)(sPl + row * 264 + 128 + lane * 4)     = q2;
            *(__nv_bfloat162*)(sPl + row * 264 + 128 + lane * 4 + 2) = q3;
        }
    }
    __syncthreads();

    // ---- load V^T [d][j] into buf1 ----
#pragma unroll
    for (int it = 0; it < 16; ++it) {
        int g = it * 256 + tid;
        int arr = g >= 2048;
        int gg = g & 2047;
        int d = gg >> 5, c = gg & 31;
        const __nv_bfloat16* src = arr ? g_vTl : g_vTh;
        uint4 val = *(const uint4*)(src + ((size_t)bh * 64 + d) * 8192 + win * 256 + c * 8);
        *(uint4*)(smem + AT_B1 + arr * 33792 + d * 528 + c * 16) = val;
    }
    __syncthreads();

    // ---- phase AV: O[64][64] = P x V -> split store into g_ah / g_al ----
    {
        uint32_t pH = sb + AT_B2, pL = sb + AT_B2 + 33792;
        uint32_t vH = sb + AT_B1, vL = sb + AT_B1 + 33792;
        int mtA = wid >> 1;
        int d0 = (wid & 1) * 32;
        float accO[4][4] = {};
#pragma unroll
        for (int ks = 0; ks < 16; ++ks) {
            uint32_t ah[4], al[4];
            uint32_t ra = (uint32_t)(mtA * 16 + aRow) * 528 + ks * 32 + aColB;
            ldsm4(ah, pH + ra);
            ldsm4(al, pL + ra);
#pragma unroll
            for (int ntl = 0; ntl < 4; ++ntl) {
                uint32_t rb = (uint32_t)(d0 + ntl * 8 + bRow) * 528 + ks * 32 + bColB;
                uint32_t bhf[2], blf[2];
                ldsm2(bhf, vH + rb);
                ldsm2(blf, vL + rb);
                mma_bf16(accO[ntl], ah, bhf);
                mma_bf16(accO[ntl], ah, blf);
                mma_bf16(accO[ntl], al, bhf);
            }
        }
        size_t row0g = (size_t)bb * 8192 + win * 256 + qt * 64;
#pragma unroll
        for (int ntl = 0; ntl < 4; ++ntl) {
            int row = mtA * 16 + (lane >> 2);
            int col = d0 + ntl * 8 + (lane & 3) * 2;
            __nv_bfloat16 h0, l0, h1, l1;
#pragma unroll
            for (int dd = 0; dd < 2; ++dd) {
                split2(accO[ntl][dd * 2 + 0], h0, l0);
                split2(accO[ntl][dd * 2 + 1], h1, l1);
                size_t idx = (row0g + row + dd * 8) * 768 + hd * 64 + col;
                __nv_bfloat162 hp = {h0, h1}, lp = {l0, l1};
                *(__nv_bfloat162*)(g_ah + idx) = hp;
                *(__nv_bfloat162*)(g_al + idx) = lp;
            }
        }
    }
}

// ---------------- launch ----------------
extern "C" void kernel_launch(void* const* d_in, const int* in_sizes, int n_in,
                              void* d_out, int out_size)
{
    const float* x    = (const float*)d_in[0];
    const float* wqkv = (const float*)d_in[1];
    const float* wout = (const float*)d_in[2];
    const float* bout = (const float*)d_in[3];
    const float* wrel = (const float*)d_in[4];
    const float* rcb  = (const float*)d_in[5];
    const float* rpb  = (const float*)d_in[6];
    float* out = (float*)d_out;

    float *P;
    __nv_bfloat16 *xh, *xl, *wqh, *wql, *woh, *wol, *ah, *al, *rkh, *rkl;
    cudaGetSymbolAddress((void**)&P,   g_P);
    cudaGetSymbolAddress((void**)&xh,  g_xh);
    cudaGetSymbolAddress((void**)&xl,  g_xl);
    cudaGetSymbolAddress((void**)&wqh, g_wqh);
    cudaGetSymbolAddress((void**)&wql, g_wql);
    cudaGetSymbolAddress((void**)&woh, g_woh);
    cudaGetSymbolAddress((void**)&wol, g_wol);
    cudaGetSymbolAddress((void**)&ah,  g_ah);
    cudaGetSymbolAddress((void**)&al,  g_al);
    cudaGetSymbolAddress((void**)&rkh, g_RKh);
    cudaGetSymbolAddress((void**)&rkl, g_RKl);

    cudaFuncSetAttribute(attn_kernel,
                         cudaFuncAttributeMaxDynamicSharedMemorySize, AT_BYTES);
    cudaFuncSetAttribute(mma_gemm<0>,
                         cudaFuncAttributeMaxDynamicSharedMemorySize, MM_BYTES);
    cudaFuncSetAttribute(mma_gemm<1>,
                         cudaFuncAttributeMaxDynamicSharedMemorySize, MM_BYTES);

    // 1) positional embedding + rel_k (SIMT, split epilogue)
    pos_kernel<<<511, 128>>>(P);
    gemm_split_kernel<<<dim3(6, 4), 256>>>(P, wrel, rkh, rkl, 511, 768, 768);

    // 2) split x and transpose-split w_qkv
    conv_split<<<16384 * 768 / 1024, 256>>>(x, xh, xl, 16384 * 768);
    conv_split_T<<<dim3(2304 / 32, 768 / 32), dim3(32, 8)>>>(wqkv, wqh, wql, 768, 2304);

    // 3) QKV projection (tensor cores; writes q fp32, k/v split bf16, v transposed)
    mma_gemm<0><<<dim3(18, 128), 256, MM_BYTES>>>(xh, xl, wqh, wql, 768,
                                                  nullptr, nullptr, 0);

    // 4) tensorized windowed attention (split epilogue -> g_ah/g_al)
    attn_kernel<<<dim3(4, 32, 24), 256, AT_BYTES>>>(rkh, rkl, rcb, rpb);

    // 5) transpose-split w_out; output projection (tensor cores) + bias
    conv_split_T<<<dim3(768 / 32, 768 / 32), dim3(32, 8)>>>(wout, woh, wol, 768, 768);
    mma_gemm<1><<<dim3(6, 128), 256, MM_BYTES>>>(ah, al, woh, wol, 768,
                                                 bout, out, 768);
}